// round 6
// baseline (speedup 1.0000x reference)
#include <cuda_runtime.h>
#include <cuda_bf16.h>
#include <cstdint>

#define DEVINL __device__ __forceinline__

constexpr int B_ = 8;
constexpr int N_ = 4096;
constexpr int D_ = 64;

// ---------------- device scratch (no allocations allowed) ----------------
__device__ float d_mu_preT[(size_t)B_ * D_ * N_];     // [B][64][N] transposed pre-embeddings (GEMM B operand)
__device__ float d_mu_pool[(size_t)B_ * N_ * D_];     // adj @ mu_pre, masked
__device__ float d_mu    [(size_t)B_ * N_ * D_];      // final node embedding mu
__device__ float d_partial[B_ * 64 * D_];             // per-64-node-block partial pooled sums
__device__ float d_c1[B_ * 32];                       // per-batch q1-path constant into qreg

// ---------------- async-copy helpers (arch-agnostic, sm_80+) ----------------
DEVINL uint32_t smem_u32(const void* p) {
    uint32_t a;
    asm("{ .reg .u64 t; cvta.to.shared.u64 t, %1; cvt.u32.u64 %0, t; }" : "=r"(a) : "l"(p));
    return a;
}
DEVINL void cp_async16(uint32_t dst, const void* src) {
    asm volatile("cp.async.cg.shared.global [%0], [%1], 16;\n" :: "r"(dst), "l"(src));
}
DEVINL void cp_commit() { asm volatile("cp.async.commit_group;\n" ::); }
#define CP_WAIT(n) asm volatile("cp.async.wait_group %0;\n" :: "n"(n))

// mma.sync m16n8k8 tf32 (A row-major, B col-major), fp32 accumulate.
DEVINL void mma_tf32(float* d, const uint32_t* a, const uint32_t* b) {
    asm volatile(
        "mma.sync.aligned.m16n8k8.row.col.f32.tf32.tf32.f32 "
        "{%0,%1,%2,%3}, {%4,%5,%6,%7}, {%8,%9}, {%0,%1,%2,%3};"
        : "+f"(d[0]), "+f"(d[1]), "+f"(d[2]), "+f"(d[3])
        : "r"(a[0]), "r"(a[1]), "r"(a[2]), "r"(a[3]), "r"(b[0]), "r"(b[1]));
}

// ---------------- 64x64 dense layer over a 64-node tile in SMEM ----------------
// Thread t: output dim = t&63, node group = t>>6 (4 groups x 16 nodes).
DEVINL void layer64(const float (*src)[68], float (*dst)[68],
                    const float* __restrict__ W, const float* __restrict__ bias,
                    int tid, bool do_relu) {
    int dout = tid & 63, grp = tid >> 6;
    float wc[64];
#pragma unroll
    for (int k = 0; k < 64; k++) wc[k] = W[k * 64 + dout];
    float bv = bias[dout];
#pragma unroll 4
    for (int j = 0; j < 16; j++) {
        int n = grp + j * 4;
        float acc = bv;
#pragma unroll
        for (int k = 0; k < 64; k += 4) {
            float4 v = *(const float4*)&src[n][k];
            acc = fmaf(v.x, wc[k + 0], acc);
            acc = fmaf(v.y, wc[k + 1], acc);
            acc = fmaf(v.z, wc[k + 2], acc);
            acc = fmaf(v.w, wc[k + 3], acc);
        }
        dst[n][dout] = do_relu ? fmaxf(acc, 0.0f) : acc;
    }
}

// ============ kernel 1: mu0 -> 2 pre layers -> mu_preT (transposed, K-major) ============
__global__ void __launch_bounds__(256) prep_kernel(
    const float* __restrict__ xv, const int* __restrict__ mask,
    const float* __restrict__ mu1,
    const float* __restrict__ preW, const float* __restrict__ preb)
{
    __shared__ __align__(16) float sA[64][68];
    __shared__ __align__(16) float sB[64][68];
    int b  = blockIdx.x >> 6;
    int n0 = (blockIdx.x & 63) << 6;
    int tid = threadIdx.x;
    int d = tid & 63, g = tid >> 6;

    for (int j = g; j < 64; j += 4) {
        int node = n0 + j;
        float x  = xv[b * N_ + node];
        float mv = (float)mask[b * N_ + node];
        sA[j][d] = fmaxf(x * mu1[d], 0.0f) * mv;
    }
    __syncthreads();
    layer64(sA, sB, preW,        preb,      tid, true);
    __syncthreads();
    layer64(sB, sA, preW + 4096, preb + 64, tid, true);
    __syncthreads();
    // coalesced transposed store: consecutive threads -> consecutive nodes
    int j = tid & 63;
    for (int dd = g; dd < 64; dd += 4)
        d_mu_preT[((size_t)b * 64 + dd) * N_ + n0 + j] = sA[j][dd];
}

// ============ kernel 2: mma.sync tf32 GEMM: mu_pool = (adj @ mu_pre) * m ============
// CTA: 128(M) x 64(N), K-chunk 32, 4 warps (32x64 warp tiles), 3-stage cp.async.
// SMEM stage: A[128][36] + B[64][36] floats (pad 36 -> conflict-free frag loads).
constexpr int A_STRIDE = 36;
constexpr int STAGE_FLOATS = 128 * A_STRIDE + 64 * A_STRIDE;  // 6912
constexpr int B_OFF_FLOATS = 128 * A_STRIDE;                  // 4608
constexpr int GEMM_SMEM = 3 * STAGE_FLOATS * 4;               // 82944 bytes

__global__ void __launch_bounds__(128, 2) gemm_kernel(
    const float* __restrict__ adj, const int* __restrict__ mask)
{
    extern __shared__ __align__(16) float smemf[];
    const uint32_t sm_base = smem_u32(smemf);
    int tid = threadIdx.x, wid = tid >> 5, lane = tid & 31;
    int b  = blockIdx.x >> 5;
    int m0 = (blockIdx.x & 31) << 7;
    const float* adjb = adj + (size_t)b * N_ * N_;
    const float* mub  = d_mu_preT + (size_t)b * 64 * N_;

    auto load_stage = [&](int slot, int chunk) {
        uint32_t base = sm_base + (uint32_t)(slot * STAGE_FLOATS) * 4u;
        int kb = chunk * 32;
        // A: 128 rows x 32 floats (128B) = 1024 x 16B ops, 8 per thread
#pragma unroll
        for (int t = 0; t < 8; t++) {
            int idx = tid + t * 128;
            int row = idx >> 3, seg = idx & 7;
            cp_async16(base + (uint32_t)(row * A_STRIDE * 4 + seg * 16),
                       adjb + (size_t)(m0 + row) * N_ + kb + seg * 4);
        }
        // B: 64 rows x 32 floats = 512 x 16B ops, 4 per thread
        uint32_t bbase = base + B_OFF_FLOATS * 4u;
#pragma unroll
        for (int t = 0; t < 4; t++) {
            int idx = tid + t * 128;
            int row = idx >> 3, seg = idx & 7;
            cp_async16(bbase + (uint32_t)(row * A_STRIDE * 4 + seg * 16),
                       mub + (size_t)row * N_ + kb + seg * 4);
        }
    };

    load_stage(0, 0); cp_commit();
    load_stage(1, 1); cp_commit();

    float acc[2][8][4];
#pragma unroll
    for (int mt = 0; mt < 2; mt++)
#pragma unroll
        for (int j = 0; j < 8; j++)
#pragma unroll
            for (int r = 0; r < 4; r++) acc[mt][j][r] = 0.0f;

    const int lr = lane >> 2;        // 0..7
    const int lc = lane & 3;         // 0..3
    const int wrow = wid * 32;       // warp M offset

    for (int c = 0; c < 128; c++) {
        CP_WAIT(1);                  // chunk c resident
        __syncthreads();
        if (c + 2 < 128) load_stage((c + 2) % 3, c + 2);
        cp_commit();

        const float* sA = smemf + (c % 3) * STAGE_FLOATS;
        const float* sB = sA + B_OFF_FLOATS;
#pragma unroll
        for (int kt = 0; kt < 4; kt++) {
            int k0 = kt * 8;
            uint32_t af[2][4], bf[8][2];
#pragma unroll
            for (int mt = 0; mt < 2; mt++) {
                int r = wrow + mt * 16 + lr;
                af[mt][0] = __float_as_uint(sA[(r    ) * A_STRIDE + k0 + lc    ]);
                af[mt][1] = __float_as_uint(sA[(r + 8) * A_STRIDE + k0 + lc    ]);
                af[mt][2] = __float_as_uint(sA[(r    ) * A_STRIDE + k0 + lc + 4]);
                af[mt][3] = __float_as_uint(sA[(r + 8) * A_STRIDE + k0 + lc + 4]);
            }
#pragma unroll
            for (int j = 0; j < 8; j++) {
                int n = j * 8 + lr;
                bf[j][0] = __float_as_uint(sB[n * A_STRIDE + k0 + lc    ]);
                bf[j][1] = __float_as_uint(sB[n * A_STRIDE + k0 + lc + 4]);
            }
#pragma unroll
            for (int mt = 0; mt < 2; mt++)
#pragma unroll
                for (int j = 0; j < 8; j++)
                    mma_tf32(acc[mt][j], af[mt], bf[j]);
        }
        __syncthreads();             // all warps done reading slot c before reuse
    }

    // epilogue: mask and store. acc frag (mt,j): rows wrow+mt*16+lr / +8, cols j*8+lc*2 / +1
#pragma unroll
    for (int mt = 0; mt < 2; mt++) {
#pragma unroll
        for (int half = 0; half < 2; half++) {
            int row = m0 + wrow + mt * 16 + lr + half * 8;
            float mv = (float)mask[b * N_ + row];
            float* dst = d_mu_pool + ((size_t)b * N_ + row) * 64;
#pragma unroll
            for (int j = 0; j < 8; j++) {
                float2 v;
                v.x = acc[mt][j][half * 2 + 0] * mv;
                v.y = acc[mt][j][half * 2 + 1] * mv;
                *(float2*)(dst + j * 8 + lc * 2) = v;
            }
        }
    }
}

// ============ kernel 3: post layers, mu2, mu, partial pooled ============
__global__ void __launch_bounds__(256) post_kernel(
    const float* __restrict__ xv, const int* __restrict__ mask,
    const float* __restrict__ mu1,
    const float* __restrict__ postW, const float* __restrict__ postb,
    const float* __restrict__ mu2W,  const float* __restrict__ mu2b)
{
    __shared__ __align__(16) float sA[64][68];
    __shared__ __align__(16) float sB[64][68];
    int b  = blockIdx.x >> 6;
    int n0 = (blockIdx.x & 63) << 6;
    int tid = threadIdx.x;
    int d = tid & 63, g = tid >> 6;

    for (int j = g; j < 64; j += 4)
        sA[j][d] = d_mu_pool[((size_t)b * N_ + n0 + j) * 64 + d];
    __syncthreads();
    layer64(sA, sB, postW,        postb,      tid, true);
    __syncthreads();
    layer64(sB, sA, postW + 4096, postb + 64, tid, true);
    __syncthreads();
    layer64(sA, sB, mu2W, mu2b, tid, false);   // sB = mu2 pre-mask
    __syncthreads();

    float part = 0.0f;
    for (int j = g; j < 64; j += 4) {
        int node = n0 + j;
        float x   = xv[b * N_ + node];
        float mv  = (float)mask[b * N_ + node];
        float m1v = fmaxf(x * mu1[d], 0.0f) * mv;
        float m2  = sB[j][d] * mv;
        float mu  = fmaxf(m1v + m2, 0.0f);
        d_mu[((size_t)b * N_ + node) * 64 + d] = mu;
        part += x * mu;
    }
    sA[g][d] = part;
    __syncthreads();
    if (tid < 64) {
        float s = sA[0][tid] + sA[1][tid] + sA[2][tid] + sA[3][tid];
        d_partial[(b * 64 + (blockIdx.x & 63)) * 64 + tid] = s;
    }
}

// ============ kernel 4: pooled reduce + q1 + fold into qreg constant ============
__global__ void pooled_kernel(
    const float* __restrict__ q1W, const float* __restrict__ q1b,
    const float* __restrict__ qregW, const float* __restrict__ qregb)
{
    int b = blockIdx.x, d = threadIdx.x;
    __shared__ float pooled[64], q1[64];
    float s = 0.0f;
    for (int k = 0; k < 64; k++) s += d_partial[(b * 64 + k) * 64 + d];
    pooled[d] = s;
    __syncthreads();
    float acc = q1b[d];
    for (int k = 0; k < 64; k++) acc = fmaf(pooled[k], q1W[k * 64 + d], acc);
    q1[d] = acc;
    __syncthreads();
    if (d < 32) {
        float c = qregb[d];
        for (int k = 0; k < 64; k++) c = fmaf(q1[k], qregW[k * 32 + d], c);
        d_c1[b * 32 + d] = c;
    }
}

// ============ kernel 5: q head ============
__global__ void __launch_bounds__(256) q_kernel(
    const int* __restrict__ mask,
    const float* __restrict__ q2W, const float* __restrict__ q2b,
    const float* __restrict__ qregW, const float* __restrict__ qW,
    const float* __restrict__ qb, float* __restrict__ out)
{
    __shared__ __align__(16) float sMu[64][68];
    __shared__ __align__(16) float sQ2[64][68];
    __shared__ float sW[64][32];
    __shared__ float sPart[64][4];
    int b  = blockIdx.x >> 6;
    int n0 = (blockIdx.x & 63) << 6;
    int tid = threadIdx.x;
    int d = tid & 63, g = tid >> 6;

    for (int j = g; j < 64; j += 4)
        sMu[j][d] = d_mu[((size_t)b * N_ + n0 + j) * 64 + d];
    for (int i = tid; i < 64 * 32; i += 256)
        sW[i >> 5][i & 31] = qregW[64 * 32 + i];    // lower half of qreg_W (q2 path)
    __syncthreads();
    layer64(sMu, sQ2, q2W, q2b, tid, false);
    __syncthreads();

    // thread: node n = tid>>2, rh block = (tid&3)*8 .. +8
    int n = tid >> 2, gq = tid & 3;
    float acc[8], wq[8];
#pragma unroll
    for (int r = 0; r < 8; r++) {
        int rh = gq * 8 + r;
        acc[r] = d_c1[b * 32 + rh];
        wq[r]  = qW[rh];
    }
#pragma unroll 8
    for (int k = 0; k < 64; k++) {
        float v = sQ2[n][k];
#pragma unroll
        for (int r = 0; r < 8; r++)
            acc[r] = fmaf(v, sW[k][gq * 8 + r], acc[r]);
    }
    float qpart = 0.0f;
#pragma unroll
    for (int r = 0; r < 8; r++) qpart = fmaf(fmaxf(acc[r], 0.0f), wq[r], qpart);
    sPart[n][gq] = qpart;
    __syncthreads();
    if (tid < 64) {
        int node = n0 + tid;
        float q = sPart[tid][0] + sPart[tid][1] + sPart[tid][2] + sPart[tid][3] + qb[0];
        q = (mask[b * N_ + node] == 0) ? -99999.0f : q;
        out[b * N_ + node] = q;
    }
}

// ================= launcher =================
extern "C" void kernel_launch(void* const* d_in, const int* in_sizes, int n_in,
                              void* d_out, int out_size) {
    const float* xv    = (const float*)d_in[0];
    const float* adj   = (const float*)d_in[2];   // edges_weight_adj (d_in[1] is the dead 'adj')
    const int*   mask  = (const int*)  d_in[3];
    const float* mu1   = (const float*)d_in[4];
    const float* mu2W  = (const float*)d_in[5];
    const float* mu2b  = (const float*)d_in[6];
    const float* preW  = (const float*)d_in[7];
    const float* preb  = (const float*)d_in[8];
    const float* postW = (const float*)d_in[9];
    const float* postb = (const float*)d_in[10];
    const float* q1W   = (const float*)d_in[11];
    const float* q1b   = (const float*)d_in[12];
    const float* q2W   = (const float*)d_in[13];
    const float* q2b   = (const float*)d_in[14];
    const float* qregW = (const float*)d_in[15];
    const float* qregb = (const float*)d_in[16];
    const float* qW    = (const float*)d_in[17];
    const float* qb    = (const float*)d_in[18];
    float* out = (float*)d_out;

    cudaFuncSetAttribute(gemm_kernel, cudaFuncAttributeMaxDynamicSharedMemorySize, GEMM_SMEM);

    prep_kernel<<<512, 256>>>(xv, mask, mu1, preW, preb);
    gemm_kernel<<<256, 128, GEMM_SMEM>>>(adj, mask);
    post_kernel<<<512, 256>>>(xv, mask, mu1, postW, postb, mu2W, mu2b);
    pooled_kernel<<<8, 64>>>(q1W, q1b, qregW, qregb);
    q_kernel<<<512, 256>>>(mask, q2W, q2b, qregW, qW, qb, out);
}

// round 7
// speedup vs baseline: 1.1077x; 1.1077x over previous
#include <cuda_runtime.h>
#include <cuda_bf16.h>
#include <cstdint>

#define DEVINL __device__ __forceinline__

constexpr int B_ = 8;
constexpr int N_ = 4096;
constexpr int D_ = 64;

// ---------------- device scratch (no allocations allowed) ----------------
__device__ uint32_t d_mu_preT_bf16[(size_t)B_ * D_ * N_ / 2]; // [B][64][N/2] bf16x2 node-pairs (GEMM B operand)
__device__ float d_mu_pool[(size_t)B_ * N_ * D_];     // adj @ mu_pre, masked
__device__ float d_mu    [(size_t)B_ * N_ * D_];      // final node embedding mu
__device__ float d_partial[B_ * 64 * D_];             // per-64-node-block partial pooled sums
__device__ float d_c1[B_ * 32];                       // per-batch q1-path constant into qreg

// ---------------- helpers ----------------
DEVINL uint32_t smem_u32(const void* p) {
    uint32_t a;
    asm("{ .reg .u64 t; cvta.to.shared.u64 t, %1; cvt.u32.u64 %0, t; }" : "=r"(a) : "l"(p));
    return a;
}
DEVINL void cp_async16(uint32_t dst, const void* src) {
    asm volatile("cp.async.cg.shared.global [%0], [%1], 16;\n" :: "r"(dst), "l"(src));
}
DEVINL void cp_commit() { asm volatile("cp.async.commit_group;\n" ::); }
#define CP_WAIT(n) asm volatile("cp.async.wait_group %0;\n" :: "n"(n))

// pack two f32 into bf16x2: lo half = first arg
DEVINL uint32_t pack_bf16x2(float lo, float hi) {
    __nv_bfloat162 v = __floats2bfloat162_rn(lo, hi);
    return *(uint32_t*)&v;
}

// mma.sync m16n8k16 bf16 (A row-major, B col-major), fp32 accumulate.
DEVINL void mma_bf16(float* d, const uint32_t* a, const uint32_t* b) {
    asm volatile(
        "mma.sync.aligned.m16n8k16.row.col.f32.bf16.bf16.f32 "
        "{%0,%1,%2,%3}, {%4,%5,%6,%7}, {%8,%9}, {%0,%1,%2,%3};"
        : "+f"(d[0]), "+f"(d[1]), "+f"(d[2]), "+f"(d[3])
        : "r"(a[0]), "r"(a[1]), "r"(a[2]), "r"(a[3]), "r"(b[0]), "r"(b[1]));
}

// ---------------- 64x64 dense layer over a 64-node tile in SMEM ----------------
// Thread t: output dim = t&63, node group = t>>6 (4 groups x 16 nodes).
DEVINL void layer64(const float (*src)[68], float (*dst)[68],
                    const float* __restrict__ W, const float* __restrict__ bias,
                    int tid, bool do_relu) {
    int dout = tid & 63, grp = tid >> 6;
    float wc[64];
#pragma unroll
    for (int k = 0; k < 64; k++) wc[k] = W[k * 64 + dout];
    float bv = bias[dout];
#pragma unroll 4
    for (int j = 0; j < 16; j++) {
        int n = grp + j * 4;
        float acc = bv;
#pragma unroll
        for (int k = 0; k < 64; k += 4) {
            float4 v = *(const float4*)&src[n][k];
            acc = fmaf(v.x, wc[k + 0], acc);
            acc = fmaf(v.y, wc[k + 1], acc);
            acc = fmaf(v.z, wc[k + 2], acc);
            acc = fmaf(v.w, wc[k + 3], acc);
        }
        dst[n][dout] = do_relu ? fmaxf(acc, 0.0f) : acc;
    }
}

// ============ kernel 1: mu0 -> 2 pre layers -> bf16 transposed mu_preT ============
__global__ void __launch_bounds__(256) prep_kernel(
    const float* __restrict__ xv, const int* __restrict__ mask,
    const float* __restrict__ mu1,
    const float* __restrict__ preW, const float* __restrict__ preb)
{
    __shared__ __align__(16) float sA[64][68];
    __shared__ __align__(16) float sB[64][68];
    __shared__ uint32_t sT[64][33];     // [dd][node-pair word], stride 33 -> conflict-free
    int b  = blockIdx.x >> 6;
    int n0 = (blockIdx.x & 63) << 6;
    int tid = threadIdx.x;
    int d = tid & 63, g = tid >> 6;

    for (int j = g; j < 64; j += 4) {
        int node = n0 + j;
        float x  = xv[b * N_ + node];
        float mv = (float)mask[b * N_ + node];
        sA[j][d] = fmaxf(x * mu1[d], 0.0f) * mv;
    }
    __syncthreads();
    layer64(sA, sB, preW, preb, tid, true);
    __syncthreads();

    // second pre layer, writing relu'd bf16 directly into transposed staging
    {
        const float* W = preW + 4096;
        float wc[64];
#pragma unroll
        for (int k = 0; k < 64; k++) wc[k] = W[k * 64 + d];
        float bv = preb[64 + d];
        __nv_bfloat16* ph = (__nv_bfloat16*)sT;
#pragma unroll 4
        for (int j = 0; j < 16; j++) {
            int n = g + j * 4;
            float acc = bv;
#pragma unroll
            for (int k = 0; k < 64; k += 4) {
                float4 v = *(const float4*)&sB[n][k];
                acc = fmaf(v.x, wc[k + 0], acc);
                acc = fmaf(v.y, wc[k + 1], acc);
                acc = fmaf(v.z, wc[k + 2], acc);
                acc = fmaf(v.w, wc[k + 3], acc);
            }
            ph[(d * 33 + (n >> 1)) * 2 + (n & 1)] = __float2bfloat16(fmaxf(acc, 0.0f));
        }
    }
    __syncthreads();

    // coalesced store of bf16x2 words: [b][dd][n0/2 + jp]
    int jp = tid & 31, ddg = tid >> 5;
#pragma unroll
    for (int t = 0; t < 8; t++) {
        int dd = ddg * 8 + t;
        d_mu_preT_bf16[((size_t)(b * 64 + dd) * N_ + n0) / 2 + jp] = sT[dd][jp];
    }
}

// ============ kernel 2: bf16 mma.sync GEMM: mu_pool = (adj @ mu_pre) * m ============
// CTA: 128(M) x 64(N), K-chunk 32, 4 warps (32x64 warp tiles), 3-stage cp.async.
// A stage: fp32 [128][36] (pad 36); B stage: bf16x2 words [64][20] (stride 20 -> conflict-free).
constexpr int A_STRIDE = 36;
constexpr int B_WSTRIDE = 20;
constexpr int A_FLOATS = 128 * A_STRIDE;                 // 4608
constexpr int STAGE_WORDS = A_FLOATS + 64 * B_WSTRIDE;   // 5888 (x4B = 23552)
constexpr int GEMM_SMEM = 3 * STAGE_WORDS * 4;           // 70656 bytes

__global__ void __launch_bounds__(128, 2) gemm_kernel(
    const float* __restrict__ adj, const int* __restrict__ mask)
{
    extern __shared__ __align__(16) float smemf[];
    const uint32_t sm_base = smem_u32(smemf);
    int tid = threadIdx.x, wid = tid >> 5, lane = tid & 31;
    int b  = blockIdx.x >> 5;
    int m0 = (blockIdx.x & 31) << 7;
    const float* adjb = adj + (size_t)b * N_ * N_;
    const uint32_t* mub = d_mu_preT_bf16 + (size_t)b * 64 * (N_ / 2);

    auto load_stage = [&](int slot, int chunk) {
        uint32_t base = sm_base + (uint32_t)(slot * STAGE_WORDS) * 4u;
        int kb = chunk * 32;
        // A: 128 rows x 32 floats (128B/row) = 1024 x 16B ops, 8 per thread
#pragma unroll
        for (int t = 0; t < 8; t++) {
            int idx = tid + t * 128;
            int row = idx >> 3, seg = idx & 7;
            cp_async16(base + (uint32_t)(row * A_STRIDE * 4 + seg * 16),
                       adjb + (size_t)(m0 + row) * N_ + kb + seg * 4);
        }
        // B: 64 rows x 32 bf16 (64B/row) = 256 x 16B ops, 2 per thread
        uint32_t bbase = base + A_FLOATS * 4u;
#pragma unroll
        for (int t = 0; t < 2; t++) {
            int idx = tid + t * 128;
            int row = idx >> 2, seg = idx & 3;
            cp_async16(bbase + (uint32_t)(row * B_WSTRIDE * 4 + seg * 16),
                       mub + (size_t)row * (N_ / 2) + kb / 2 + seg * 4);
        }
    };

    load_stage(0, 0); cp_commit();
    load_stage(1, 1); cp_commit();

    float acc[2][8][4];
#pragma unroll
    for (int mt = 0; mt < 2; mt++)
#pragma unroll
        for (int j = 0; j < 8; j++)
#pragma unroll
            for (int r = 0; r < 4; r++) acc[mt][j][r] = 0.0f;

    const int lr = lane >> 2;        // 0..7
    const int lc = lane & 3;         // 0..3
    const int wrow = wid * 32;       // warp M offset

    for (int c = 0; c < 128; c++) {
        CP_WAIT(1);                  // chunk c resident
        __syncthreads();
        if (c + 2 < 128) load_stage((c + 2) % 3, c + 2);
        cp_commit();

        const float* sA = smemf + (c % 3) * STAGE_WORDS;
        const uint32_t* sB = (const uint32_t*)(sA + A_FLOATS);
#pragma unroll
        for (int kt = 0; kt < 2; kt++) {       // two k16 groups per chunk
            int k0 = kt * 16;
            uint32_t af[2][4], bf[8][2];
#pragma unroll
            for (int mt = 0; mt < 2; mt++) {
                int r = wrow + mt * 16 + lr;
                float2 p0 = *(const float2*)&sA[(r    ) * A_STRIDE + k0 + 2 * lc    ];
                float2 p1 = *(const float2*)&sA[(r + 8) * A_STRIDE + k0 + 2 * lc    ];
                float2 p2 = *(const float2*)&sA[(r    ) * A_STRIDE + k0 + 2 * lc + 8];
                float2 p3 = *(const float2*)&sA[(r + 8) * A_STRIDE + k0 + 2 * lc + 8];
                af[mt][0] = pack_bf16x2(p0.x, p0.y);
                af[mt][1] = pack_bf16x2(p1.x, p1.y);
                af[mt][2] = pack_bf16x2(p2.x, p2.y);
                af[mt][3] = pack_bf16x2(p3.x, p3.y);
            }
            int kw0 = kt * 8 + lc;
#pragma unroll
            for (int j = 0; j < 8; j++) {
                int n = j * 8 + lr;
                bf[j][0] = sB[n * B_WSTRIDE + kw0    ];
                bf[j][1] = sB[n * B_WSTRIDE + kw0 + 4];
            }
#pragma unroll
            for (int mt = 0; mt < 2; mt++)
#pragma unroll
                for (int j = 0; j < 8; j++)
                    mma_bf16(acc[mt][j], af[mt], bf[j]);
        }
        __syncthreads();             // all warps done reading slot c before reuse
    }

    // epilogue: mask and store. frag (mt,j): rows wrow+mt*16+lr / +8, cols j*8+lc*2 / +1
#pragma unroll
    for (int mt = 0; mt < 2; mt++) {
#pragma unroll
        for (int half = 0; half < 2; half++) {
            int row = m0 + wrow + mt * 16 + lr + half * 8;
            float mv = (float)mask[b * N_ + row];
            float* dst = d_mu_pool + ((size_t)b * N_ + row) * 64;
#pragma unroll
            for (int j = 0; j < 8; j++) {
                float2 v;
                v.x = acc[mt][j][half * 2 + 0] * mv;
                v.y = acc[mt][j][half * 2 + 1] * mv;
                *(float2*)(dst + j * 8 + lc * 2) = v;
            }
        }
    }
}

// ============ kernel 3: post layers, mu2, mu, partial pooled ============
__global__ void __launch_bounds__(256) post_kernel(
    const float* __restrict__ xv, const int* __restrict__ mask,
    const float* __restrict__ mu1,
    const float* __restrict__ postW, const float* __restrict__ postb,
    const float* __restrict__ mu2W,  const float* __restrict__ mu2b)
{
    __shared__ __align__(16) float sA[64][68];
    __shared__ __align__(16) float sB[64][68];
    int b  = blockIdx.x >> 6;
    int n0 = (blockIdx.x & 63) << 6;
    int tid = threadIdx.x;
    int d = tid & 63, g = tid >> 6;

    for (int j = g; j < 64; j += 4)
        sA[j][d] = d_mu_pool[((size_t)b * N_ + n0 + j) * 64 + d];
    __syncthreads();
    layer64(sA, sB, postW,        postb,      tid, true);
    __syncthreads();
    layer64(sB, sA, postW + 4096, postb + 64, tid, true);
    __syncthreads();
    layer64(sA, sB, mu2W, mu2b, tid, false);   // sB = mu2 pre-mask
    __syncthreads();

    float part = 0.0f;
    for (int j = g; j < 64; j += 4) {
        int node = n0 + j;
        float x   = xv[b * N_ + node];
        float mv  = (float)mask[b * N_ + node];
        float m1v = fmaxf(x * mu1[d], 0.0f) * mv;
        float m2  = sB[j][d] * mv;
        float mu  = fmaxf(m1v + m2, 0.0f);
        d_mu[((size_t)b * N_ + node) * 64 + d] = mu;
        part += x * mu;
    }
    sA[g][d] = part;
    __syncthreads();
    if (tid < 64) {
        float s = sA[0][tid] + sA[1][tid] + sA[2][tid] + sA[3][tid];
        d_partial[(b * 64 + (blockIdx.x & 63)) * 64 + tid] = s;
    }
}

// ============ kernel 4: pooled reduce + q1 + fold into qreg constant ============
__global__ void __launch_bounds__(256) pooled_kernel(
    const float* __restrict__ q1W, const float* __restrict__ q1b,
    const float* __restrict__ qregW, const float* __restrict__ qregb)
{
    int b = blockIdx.x, tid = threadIdx.x;
    int d = tid & 63, g = tid >> 6;
    __shared__ float red[4][64];
    __shared__ float pooled[64], q1[64];
    float s = 0.0f;
#pragma unroll 4
    for (int k = g; k < 64; k += 4) s += d_partial[(b * 64 + k) * 64 + d];
    red[g][d] = s;
    __syncthreads();
    if (tid < 64) pooled[tid] = red[0][tid] + red[1][tid] + red[2][tid] + red[3][tid];
    __syncthreads();
    float a = (g == 0) ? q1b[d] : 0.0f;
#pragma unroll 4
    for (int k = g; k < 64; k += 4) a = fmaf(pooled[k], q1W[k * 64 + d], a);
    red[g][d] = a;
    __syncthreads();
    if (tid < 64) q1[tid] = red[0][tid] + red[1][tid] + red[2][tid] + red[3][tid];
    __syncthreads();
    if (tid < 32) {
        float c = qregb[tid];
#pragma unroll 8
        for (int k = 0; k < 64; k++) c = fmaf(q1[k], qregW[k * 32 + tid], c);
        d_c1[b * 32 + tid] = c;
    }
}

// ============ kernel 5: q head ============
__global__ void __launch_bounds__(256) q_kernel(
    const int* __restrict__ mask,
    const float* __restrict__ q2W, const float* __restrict__ q2b,
    const float* __restrict__ qregW, const float* __restrict__ qW,
    const float* __restrict__ qb, float* __restrict__ out)
{
    __shared__ __align__(16) float sMu[64][68];
    __shared__ __align__(16) float sQ2[64][68];
    __shared__ float sW[64][32];
    __shared__ float sPart[64][4];
    int b  = blockIdx.x >> 6;
    int n0 = (blockIdx.x & 63) << 6;
    int tid = threadIdx.x;
    int d = tid & 63, g = tid >> 6;

    for (int j = g; j < 64; j += 4)
        sMu[j][d] = d_mu[((size_t)b * N_ + n0 + j) * 64 + d];
    for (int i = tid; i < 64 * 32; i += 256)
        sW[i >> 5][i & 31] = qregW[64 * 32 + i];    // lower half of qreg_W (q2 path)
    __syncthreads();
    layer64(sMu, sQ2, q2W, q2b, tid, false);
    __syncthreads();

    // thread: node n = tid>>2, rh block = (tid&3)*8 .. +8
    int n = tid >> 2, gq = tid & 3;
    float acc[8], wq[8];
#pragma unroll
    for (int r = 0; r < 8; r++) {
        int rh = gq * 8 + r;
        acc[r] = d_c1[b * 32 + rh];
        wq[r]  = qW[rh];
    }
#pragma unroll 8
    for (int k = 0; k < 64; k++) {
        float v = sQ2[n][k];
#pragma unroll
        for (int r = 0; r < 8; r++)
            acc[r] = fmaf(v, sW[k][gq * 8 + r], acc[r]);
    }
    float qpart = 0.0f;
#pragma unroll
    for (int r = 0; r < 8; r++) qpart = fmaf(fmaxf(acc[r], 0.0f), wq[r], qpart);
    sPart[n][gq] = qpart;
    __syncthreads();
    if (tid < 64) {
        int node = n0 + tid;
        float q = sPart[tid][0] + sPart[tid][1] + sPart[tid][2] + sPart[tid][3] + qb[0];
        q = (mask[b * N_ + node] == 0) ? -99999.0f : q;
        out[b * N_ + node] = q;
    }
}

// ================= launcher =================
extern "C" void kernel_launch(void* const* d_in, const int* in_sizes, int n_in,
                              void* d_out, int out_size) {
    const float* xv    = (const float*)d_in[0];
    const float* adj   = (const float*)d_in[2];   // edges_weight_adj (d_in[1] is the dead 'adj')
    const int*   mask  = (const int*)  d_in[3];
    const float* mu1   = (const float*)d_in[4];
    const float* mu2W  = (const float*)d_in[5];
    const float* mu2b  = (const float*)d_in[6];
    const float* preW  = (const float*)d_in[7];
    const float* preb  = (const float*)d_in[8];
    const float* postW = (const float*)d_in[9];
    const float* postb = (const float*)d_in[10];
    const float* q1W   = (const float*)d_in[11];
    const float* q1b   = (const float*)d_in[12];
    const float* q2W   = (const float*)d_in[13];
    const float* q2b   = (const float*)d_in[14];
    const float* qregW = (const float*)d_in[15];
    const float* qregb = (const float*)d_in[16];
    const float* qW    = (const float*)d_in[17];
    const float* qb    = (const float*)d_in[18];
    float* out = (float*)d_out;

    cudaFuncSetAttribute(gemm_kernel, cudaFuncAttributeMaxDynamicSharedMemorySize, GEMM_SMEM);

    prep_kernel<<<512, 256>>>(xv, mask, mu1, preW, preb);
    gemm_kernel<<<256, 128, GEMM_SMEM>>>(adj, mask);
    post_kernel<<<512, 256>>>(xv, mask, mu1, postW, postb, mu2W, mu2b);
    pooled_kernel<<<8, 256>>>(q1W, q1b, qregW, qregb);
    q_kernel<<<512, 256>>>(mask, q2W, q2b, qregW, qW, qb, out);
}

// round 8
// speedup vs baseline: 1.3233x; 1.1946x over previous
#include <cuda_runtime.h>
#include <cuda_bf16.h>
#include <cstdint>

#define DEVINL __device__ __forceinline__

constexpr int B_ = 8;
constexpr int N_ = 4096;

// ---------------- device scratch (no allocations allowed) ----------------
__device__ uint32_t d_mu_preT_bf16[(size_t)B_ * 64 * (N_ / 2)]; // [B][64][N/2] bf16x2 node-pairs (GEMM B)
__device__ uint32_t d_mu_pool_b16[(size_t)B_ * N_ * 32];        // [B][N][32 kwords] bf16x2 dim-pairs
__device__ uint32_t d_mu_b16[(size_t)B_ * N_ * 32];             // final mu, bf16x2 dim-pairs
__device__ float    d_partial[B_ * 64 * 64];                    // per-64-node-block pooled partials
__device__ uint32_t d_wT[6 * 2048];                             // 6 layers of W^T bf16 [dout][32 kwords]
__device__ uint32_t d_wTq[1024];                                // qregW lower half W^T [rh][32 kwords]

// ---------------- helpers ----------------
DEVINL uint32_t smem_u32(const void* p) {
    uint32_t a;
    asm("{ .reg .u64 t; cvta.to.shared.u64 t, %1; cvt.u32.u64 %0, t; }" : "=r"(a) : "l"(p));
    return a;
}
DEVINL void cp_async16(uint32_t dst, const void* src) {
    asm volatile("cp.async.cg.shared.global [%0], [%1], 16;\n" :: "r"(dst), "l"(src));
}
DEVINL void cp_commit() { asm volatile("cp.async.commit_group;\n" ::); }
#define CP_WAIT(n) asm volatile("cp.async.wait_group %0;\n" :: "n"(n))

DEVINL uint32_t pack_bf16x2(float lo, float hi) {
    __nv_bfloat162 v = __floats2bfloat162_rn(lo, hi);
    return *(uint32_t*)&v;
}

// mma.sync m16n8k16 bf16 (A row-major, B col-major), fp32 accumulate.
DEVINL void mma_bf16(float* d, const uint32_t* a, const uint32_t* b) {
    asm volatile(
        "mma.sync.aligned.m16n8k16.row.col.f32.bf16.bf16.f32 "
        "{%0,%1,%2,%3}, {%4,%5,%6,%7}, {%8,%9}, {%0,%1,%2,%3};"
        : "+f"(d[0]), "+f"(d[1]), "+f"(d[2]), "+f"(d[3])
        : "r"(a[0]), "r"(a[1]), "r"(a[2]), "r"(a[3]), "r"(b[0]), "r"(b[1]));
}

// ---------------- register-resident 64-wide layer primitives ----------------
// Fragment convention (per warp, m-tile of 16 rows):
//   activation words w[j][0] = rows lr,    cols j*8+2lc, j*8+2lc+1 (bf16x2)
//   activation words w[j][1] = rows lr+8,  same cols
// This layout is simultaneously the mma C-fragment (pair-packed) and the
// A-fragment (kword j*4+lc) of the next layer -> layers chain in registers.

DEVINL void init_bias(float acc[8][4], const float* __restrict__ bias, int lc) {
#pragma unroll
    for (int j = 0; j < 8; j++) {
        float b0 = bias[j * 8 + 2 * lc], b1 = bias[j * 8 + 2 * lc + 1];
        acc[j][0] = b0; acc[j][1] = b1; acc[j][2] = b0; acc[j][3] = b1;
    }
}
DEVINL void pack_words(const float acc[8][4], uint32_t w[8][2], bool relu) {
#pragma unroll
    for (int j = 0; j < 8; j++) {
        float a0 = acc[j][0], a1 = acc[j][1], a2 = acc[j][2], a3 = acc[j][3];
        if (relu) { a0 = fmaxf(a0, 0.f); a1 = fmaxf(a1, 0.f); a2 = fmaxf(a2, 0.f); a3 = fmaxf(a3, 0.f); }
        w[j][0] = pack_bf16x2(a0, a1);
        w[j][1] = pack_bf16x2(a2, a3);
    }
}
// one 64x64 layer: acc (pre-initialized with bias) += X(w) @ W^T(wT)
DEVINL void layer_mma(float acc[8][4], const uint32_t w[8][2],
                      const uint32_t* __restrict__ wT, int lr, int lc) {
#pragma unroll
    for (int kt = 0; kt < 4; kt++) {
        uint32_t a[4] = { w[2 * kt][0], w[2 * kt][1], w[2 * kt + 1][0], w[2 * kt + 1][1] };
#pragma unroll
        for (int j = 0; j < 8; j++) {
            uint32_t bb[2];
            bb[0] = wT[(j * 8 + lr) * 32 + kt * 8 + lc];
            bb[1] = wT[(j * 8 + lr) * 32 + kt * 8 + lc + 4];
            mma_bf16(acc[j], a, bb);
        }
    }
}

// ============ kernel 0: convert all layer weights to bf16 W^T ============
__global__ void wprep_kernel(
    const float* __restrict__ preW, const float* __restrict__ postW,
    const float* __restrict__ mu2W, const float* __restrict__ q2W,
    const float* __restrict__ qregW)
{
    int tid = threadIdx.x;
    for (int idx = tid; idx < 6 * 2048; idx += 256) {
        int l = idx >> 11, r = idx & 2047, dout = r >> 5, kw = r & 31;
        const float* W;
        switch (l) {
            case 0: W = preW;         break;
            case 1: W = preW + 4096;  break;
            case 2: W = postW;        break;
            case 3: W = postW + 4096; break;
            case 4: W = mu2W;         break;
            default: W = q2W;         break;
        }
        d_wT[idx] = pack_bf16x2(W[(2 * kw) * 64 + dout], W[(2 * kw + 1) * 64 + dout]);
    }
    for (int idx = tid; idx < 1024; idx += 256) {
        int rh = idx >> 5, kw = idx & 31;
        d_wTq[idx] = pack_bf16x2(qregW[(64 + 2 * kw) * 32 + rh],
                                 qregW[(64 + 2 * kw + 1) * 32 + rh]);
    }
}

// ============ kernel 1: mu0 -> 2 pre layers -> transposed bf16 mu_preT ============
__global__ void __launch_bounds__(128) prep_kernel(
    const float* __restrict__ xv, const int* __restrict__ mask,
    const float* __restrict__ mu1, const float* __restrict__ preb)
{
    __shared__ uint32_t sS[64 * 36];    // [node][kword], stride 36 -> conflict-free
    int b  = blockIdx.x >> 6;
    int n0 = (blockIdx.x & 63) << 6;
    int tid = threadIdx.x, wid = tid >> 5, lane = tid & 31;
    int lr = lane >> 2, lc = lane & 3;
    int rl0 = wid * 16 + lr;
    int row0 = n0 + rl0;

    float xv0 = xv[b * N_ + row0],     xv8 = xv[b * N_ + row0 + 8];
    float mv0 = (float)mask[b * N_ + row0], mv8 = (float)mask[b * N_ + row0 + 8];

    uint32_t w[8][2];
#pragma unroll
    for (int j = 0; j < 8; j++) {
        int c0 = j * 8 + 2 * lc;
        float u0 = mu1[c0], u1 = mu1[c0 + 1];
        w[j][0] = pack_bf16x2(fmaxf(xv0 * u0, 0.f) * mv0, fmaxf(xv0 * u1, 0.f) * mv0);
        w[j][1] = pack_bf16x2(fmaxf(xv8 * u0, 0.f) * mv8, fmaxf(xv8 * u1, 0.f) * mv8);
    }
    float acc[8][4];
    init_bias(acc, preb, lc);       layer_mma(acc, w, d_wT,        lr, lc); pack_words(acc, w, true);
    init_bias(acc, preb + 64, lc);  layer_mma(acc, w, d_wT + 2048, lr, lc); pack_words(acc, w, true);

#pragma unroll
    for (int j = 0; j < 8; j++) {
        sS[rl0 * 36 + j * 4 + lc]       = w[j][0];
        sS[(rl0 + 8) * 36 + j * 4 + lc] = w[j][1];
    }
    __syncthreads();

    // transpose: word (dd, node-pair jp) = (bf16(node 2jp, dd), bf16(node 2jp+1, dd))
    int jp = tid & 31;
#pragma unroll
    for (int t = 0; t < 16; t++) {
        int dd = (tid >> 5) + t * 4;
        uint32_t w0 = sS[(2 * jp) * 36 + (dd >> 1)];
        uint32_t w1 = sS[(2 * jp + 1) * 36 + (dd >> 1)];
        uint32_t out = __byte_perm(w0, w1, (dd & 1) ? 0x7632 : 0x5410);
        d_mu_preT_bf16[(size_t)(b * 64 + dd) * (N_ / 2) + (n0 >> 1) + jp] = out;
    }
}

// ============ kernel 2: bf16 mma.sync GEMM: mu_pool = (adj @ mu_pre) * m ============
constexpr int A_STRIDE = 36;
constexpr int B_WSTRIDE = 20;
constexpr int A_FLOATS = 128 * A_STRIDE;
constexpr int STAGE_WORDS = A_FLOATS + 64 * B_WSTRIDE;
constexpr int GEMM_SMEM = 3 * STAGE_WORDS * 4;

__global__ void __launch_bounds__(128, 2) gemm_kernel(
    const float* __restrict__ adj, const int* __restrict__ mask)
{
    extern __shared__ __align__(16) float smemf[];
    const uint32_t sm_base = smem_u32(smemf);
    int tid = threadIdx.x, wid = tid >> 5, lane = tid & 31;
    int b  = blockIdx.x >> 5;
    int m0 = (blockIdx.x & 31) << 7;
    const float* adjb = adj + (size_t)b * N_ * N_;
    const uint32_t* mub = d_mu_preT_bf16 + (size_t)b * 64 * (N_ / 2);

    auto load_stage = [&](int slot, int chunk) {
        uint32_t base = sm_base + (uint32_t)(slot * STAGE_WORDS) * 4u;
        int kb = chunk * 32;
#pragma unroll
        for (int t = 0; t < 8; t++) {
            int idx = tid + t * 128;
            int row = idx >> 3, seg = idx & 7;
            cp_async16(base + (uint32_t)(row * A_STRIDE * 4 + seg * 16),
                       adjb + (size_t)(m0 + row) * N_ + kb + seg * 4);
        }
        uint32_t bbase = base + A_FLOATS * 4u;
#pragma unroll
        for (int t = 0; t < 2; t++) {
            int idx = tid + t * 128;
            int row = idx >> 2, seg = idx & 3;
            cp_async16(bbase + (uint32_t)(row * B_WSTRIDE * 4 + seg * 16),
                       mub + (size_t)row * (N_ / 2) + kb / 2 + seg * 4);
        }
    };

    load_stage(0, 0); cp_commit();
    load_stage(1, 1); cp_commit();

    float acc[2][8][4];
#pragma unroll
    for (int mt = 0; mt < 2; mt++)
#pragma unroll
        for (int j = 0; j < 8; j++)
#pragma unroll
            for (int r = 0; r < 4; r++) acc[mt][j][r] = 0.0f;

    const int lr = lane >> 2, lc = lane & 3;
    const int wrow = wid * 32;

    for (int c = 0; c < 128; c++) {
        CP_WAIT(1);
        __syncthreads();             // visibility of all threads' cp.async + slot-reuse guard
        if (c + 2 < 128) load_stage((c + 2) % 3, c + 2);
        cp_commit();

        const float* sA = smemf + (c % 3) * STAGE_WORDS;
        const uint32_t* sB = (const uint32_t*)(sA + A_FLOATS);
#pragma unroll
        for (int kt = 0; kt < 2; kt++) {
            int k0 = kt * 16;
            uint32_t af[2][4], bf[8][2];
#pragma unroll
            for (int mt = 0; mt < 2; mt++) {
                int r = wrow + mt * 16 + lr;
                float2 p0 = *(const float2*)&sA[(r    ) * A_STRIDE + k0 + 2 * lc    ];
                float2 p1 = *(const float2*)&sA[(r + 8) * A_STRIDE + k0 + 2 * lc    ];
                float2 p2 = *(const float2*)&sA[(r    ) * A_STRIDE + k0 + 2 * lc + 8];
                float2 p3 = *(const float2*)&sA[(r + 8) * A_STRIDE + k0 + 2 * lc + 8];
                af[mt][0] = pack_bf16x2(p0.x, p0.y);
                af[mt][1] = pack_bf16x2(p1.x, p1.y);
                af[mt][2] = pack_bf16x2(p2.x, p2.y);
                af[mt][3] = pack_bf16x2(p3.x, p3.y);
            }
            int kw0 = kt * 8 + lc;
#pragma unroll
            for (int j = 0; j < 8; j++) {
                int n = j * 8 + lr;
                bf[j][0] = sB[n * B_WSTRIDE + kw0    ];
                bf[j][1] = sB[n * B_WSTRIDE + kw0 + 4];
            }
#pragma unroll
            for (int mt = 0; mt < 2; mt++)
#pragma unroll
                for (int j = 0; j < 8; j++)
                    mma_bf16(acc[mt][j], af[mt], bf[j]);
        }
        // no trailing barrier: next iteration's post-CP_WAIT barrier guards slot reuse
    }

    // epilogue: mask, pack bf16, store kword layout [row][j*4+lc]
#pragma unroll
    for (int mt = 0; mt < 2; mt++) {
#pragma unroll
        for (int half = 0; half < 2; half++) {
            int row = m0 + wrow + mt * 16 + lr + half * 8;
            float mv = (float)mask[b * N_ + row];
            uint32_t* dst = d_mu_pool_b16 + (size_t)(b * N_ + row) * 32;
#pragma unroll
            for (int j = 0; j < 8; j++)
                dst[j * 4 + lc] = pack_bf16x2(acc[mt][j][half * 2] * mv,
                                              acc[mt][j][half * 2 + 1] * mv);
        }
    }
}

// ============ kernel 3: post layers, mu2, mu, pooled partials ============
__global__ void __launch_bounds__(128) post_kernel(
    const float* __restrict__ xv, const int* __restrict__ mask,
    const float* __restrict__ mu1,
    const float* __restrict__ postb, const float* __restrict__ mu2b)
{
    __shared__ float sP[4][64];
    int b  = blockIdx.x >> 6;
    int n0 = (blockIdx.x & 63) << 6;
    int tid = threadIdx.x, wid = tid >> 5, lane = tid & 31;
    int lr = lane >> 2, lc = lane & 3;
    int row0 = n0 + wid * 16 + lr;

    uint32_t w[8][2];
    {
        const uint32_t* src = d_mu_pool_b16 + (size_t)(b * N_ + row0) * 32;
#pragma unroll
        for (int j = 0; j < 8; j++) {
            w[j][0] = src[j * 4 + lc];
            w[j][1] = src[8 * 32 + j * 4 + lc];
        }
    }
    float acc[8][4];
    init_bias(acc, postb, lc);      layer_mma(acc, w, d_wT + 2 * 2048, lr, lc); pack_words(acc, w, true);
    init_bias(acc, postb + 64, lc); layer_mma(acc, w, d_wT + 3 * 2048, lr, lc); pack_words(acc, w, true);
    init_bias(acc, mu2b, lc);       layer_mma(acc, w, d_wT + 4 * 2048, lr, lc); // mu2, no relu

    float xv0 = xv[b * N_ + row0],     xv8 = xv[b * N_ + row0 + 8];
    float mv0 = (float)mask[b * N_ + row0], mv8 = (float)mask[b * N_ + row0 + 8];
    uint32_t* dst = d_mu_b16 + (size_t)(b * N_ + row0) * 32;

    float ps[8][2];
#pragma unroll
    for (int j = 0; j < 8; j++) {
        int c0 = j * 8 + 2 * lc;
        float u0 = mu1[c0], u1 = mu1[c0 + 1];
        float v00 = fmaxf(fmaxf(xv0 * u0, 0.f) * mv0 + acc[j][0] * mv0, 0.f);
        float v01 = fmaxf(fmaxf(xv0 * u1, 0.f) * mv0 + acc[j][1] * mv0, 0.f);
        float v80 = fmaxf(fmaxf(xv8 * u0, 0.f) * mv8 + acc[j][2] * mv8, 0.f);
        float v81 = fmaxf(fmaxf(xv8 * u1, 0.f) * mv8 + acc[j][3] * mv8, 0.f);
        dst[j * 4 + lc]          = pack_bf16x2(v00, v01);
        dst[8 * 32 + j * 4 + lc] = pack_bf16x2(v80, v81);
        ps[j][0] = xv0 * v00 + xv8 * v80;
        ps[j][1] = xv0 * v01 + xv8 * v81;
    }
    // reduce over the warp's 16 rows (lr lanes), then across warps via smem
#pragma unroll
    for (int j = 0; j < 8; j++) {
#pragma unroll
        for (int h = 0; h < 2; h++) {
            float t = ps[j][h];
            t += __shfl_xor_sync(0xffffffffu, t, 4);
            t += __shfl_xor_sync(0xffffffffu, t, 8);
            t += __shfl_xor_sync(0xffffffffu, t, 16);
            if (lr == 0) sP[wid][j * 8 + 2 * lc + h] = t;
        }
    }
    __syncthreads();
    if (tid < 64)
        d_partial[(b * 64 + (blockIdx.x & 63)) * 64 + tid] =
            sP[0][tid] + sP[1][tid] + sP[2][tid] + sP[3][tid];
}

// ============ kernel 4: q head (includes redundant pooled->q1->c1 fold) ============
__global__ void __launch_bounds__(128) q_kernel(
    const int* __restrict__ mask,
    const float* __restrict__ q1W, const float* __restrict__ q1b,
    const float* __restrict__ qregW, const float* __restrict__ qregb,
    const float* __restrict__ q2b,
    const float* __restrict__ qW, const float* __restrict__ qb,
    float* __restrict__ out)
{
    __shared__ float pooled[64], q1s[64], c1s[32];
    int b  = blockIdx.x >> 6;
    int n0 = (blockIdx.x & 63) << 6;
    int tid = threadIdx.x, wid = tid >> 5, lane = tid & 31;
    int lr = lane >> 2, lc = lane & 3;

    if (tid < 64) {
        float s = 0.f;
#pragma unroll 8
        for (int t = 0; t < 64; t++) s += d_partial[(b * 64 + t) * 64 + tid];
        pooled[tid] = s;
    }
    __syncthreads();
    if (tid < 64) {
        float a = q1b[tid];
#pragma unroll 8
        for (int k = 0; k < 64; k++) a = fmaf(pooled[k], q1W[k * 64 + tid], a);
        q1s[tid] = a;
    }
    __syncthreads();
    if (tid < 32) {
        float c = qregb[tid];
#pragma unroll 8
        for (int k = 0; k < 64; k++) c = fmaf(q1s[k], qregW[k * 32 + tid], c);
        c1s[tid] = c;
    }
    __syncthreads();

    int row0 = n0 + wid * 16 + lr;
    uint32_t w[8][2];
    {
        const uint32_t* src = d_mu_b16 + (size_t)(b * N_ + row0) * 32;
#pragma unroll
        for (int j = 0; j < 8; j++) {
            w[j][0] = src[j * 4 + lc];
            w[j][1] = src[8 * 32 + j * 4 + lc];
        }
    }
    float acc[8][4];
    init_bias(acc, q2b, lc);
    layer_mma(acc, w, d_wT + 5 * 2048, lr, lc);     // q2 = mu @ q2_W + b (no relu)
    pack_words(acc, w, false);

    // qreg mma: N=32, acc init = c1 (q1-path constant)
    float qa[4][4];
#pragma unroll
    for (int j = 0; j < 4; j++) {
        int c0 = j * 8 + 2 * lc;
        qa[j][0] = qa[j][2] = c1s[c0];
        qa[j][1] = qa[j][3] = c1s[c0 + 1];
    }
#pragma unroll
    for (int kt = 0; kt < 4; kt++) {
        uint32_t a[4] = { w[2 * kt][0], w[2 * kt][1], w[2 * kt + 1][0], w[2 * kt + 1][1] };
#pragma unroll
        for (int j = 0; j < 4; j++) {
            uint32_t bb[2];
            bb[0] = d_wTq[(j * 8 + lr) * 32 + kt * 8 + lc];
            bb[1] = d_wTq[(j * 8 + lr) * 32 + kt * 8 + lc + 4];
            mma_bf16(qa[j], a, bb);
        }
    }
    // relu, multiply qW, row-sum over 32 cols
    float s0 = 0.f, s8 = 0.f;
#pragma unroll
    for (int j = 0; j < 4; j++) {
        int c0 = j * 8 + 2 * lc;
        float wq0 = qW[c0], wq1 = qW[c0 + 1];
        s0 += fmaxf(qa[j][0], 0.f) * wq0 + fmaxf(qa[j][1], 0.f) * wq1;
        s8 += fmaxf(qa[j][2], 0.f) * wq0 + fmaxf(qa[j][3], 0.f) * wq1;
    }
    s0 += __shfl_xor_sync(0xffffffffu, s0, 1);
    s0 += __shfl_xor_sync(0xffffffffu, s0, 2);
    s8 += __shfl_xor_sync(0xffffffffu, s8, 1);
    s8 += __shfl_xor_sync(0xffffffffu, s8, 2);
    if (lc == 0) {
        float q0 = s0 + qb[0], q8 = s8 + qb[0];
        if (mask[b * N_ + row0] == 0)     q0 = -99999.0f;
        if (mask[b * N_ + row0 + 8] == 0) q8 = -99999.0f;
        out[b * N_ + row0]     = q0;
        out[b * N_ + row0 + 8] = q8;
    }
}

// ================= launcher =================
extern "C" void kernel_launch(void* const* d_in, const int* in_sizes, int n_in,
                              void* d_out, int out_size) {
    const float* xv    = (const float*)d_in[0];
    const float* adj   = (const float*)d_in[2];   // edges_weight_adj (d_in[1] is the dead 'adj')
    const int*   mask  = (const int*)  d_in[3];
    const float* mu1   = (const float*)d_in[4];
    const float* mu2W  = (const float*)d_in[5];
    const float* mu2b  = (const float*)d_in[6];
    const float* preW  = (const float*)d_in[7];
    const float* preb  = (const float*)d_in[8];
    const float* postW = (const float*)d_in[9];
    const float* postb = (const float*)d_in[10];
    const float* q1W   = (const float*)d_in[11];
    const float* q1b   = (const float*)d_in[12];
    const float* q2W   = (const float*)d_in[13];
    const float* q2b   = (const float*)d_in[14];
    const float* qregW = (const float*)d_in[15];
    const float* qregb = (const float*)d_in[16];
    const float* qW    = (const float*)d_in[17];
    const float* qb    = (const float*)d_in[18];
    float* out = (float*)d_out;

    cudaFuncSetAttribute(gemm_kernel, cudaFuncAttributeMaxDynamicSharedMemorySize, GEMM_SMEM);

    wprep_kernel<<<1, 256>>>(preW, postW, mu2W, q2W, qregW);
    prep_kernel<<<512, 128>>>(xv, mask, mu1, preb);
    gemm_kernel<<<256, 128, GEMM_SMEM>>>(adj, mask);
    post_kernel<<<512, 128>>>(xv, mask, mu1, postb, mu2b);
    q_kernel<<<512, 128>>>(mask, q1W, q1b, qregW, qregb, q2b, qW, qb, out);
}

// round 9
// speedup vs baseline: 1.3960x; 1.0550x over previous
#include <cuda_runtime.h>
#include <cuda_bf16.h>
#include <cstdint>

#define DEVINL __device__ __forceinline__

constexpr int B_ = 8;
constexpr int N_ = 4096;

// ---------------- device scratch (no allocations allowed) ----------------
__device__ uint32_t d_mu_preT_bf16[(size_t)B_ * 64 * (N_ / 2)]; // [B][64][N/2] bf16x2 node-pairs (GEMM B)
__device__ uint32_t d_mu_pool_b16[(size_t)B_ * N_ * 32];        // [B][N][32 kwords] bf16x2 dim-pairs
__device__ uint32_t d_mu_b16[(size_t)B_ * N_ * 32];             // final mu, bf16x2 dim-pairs
__device__ float    d_partial[B_ * 32 * 64];                    // per-128-node-block pooled partials
__device__ uint32_t d_wT[6 * 2048];                             // 6 layers of W^T bf16 [dout][32 kwords]
__device__ uint32_t d_wTq[1024];                                // qregW lower half W^T [rh][32 kwords]

// ---------------- helpers ----------------
DEVINL uint32_t smem_u32(const void* p) {
    uint32_t a;
    asm("{ .reg .u64 t; cvta.to.shared.u64 t, %1; cvt.u32.u64 %0, t; }" : "=r"(a) : "l"(p));
    return a;
}
DEVINL void cp_async16(uint32_t dst, const void* src) {
    asm volatile("cp.async.cg.shared.global [%0], [%1], 16;\n" :: "r"(dst), "l"(src));
}
DEVINL void cp_commit() { asm volatile("cp.async.commit_group;\n" ::); }
#define CP_WAIT(n) asm volatile("cp.async.wait_group %0;\n" :: "n"(n))

DEVINL uint32_t pack_bf16x2(float lo, float hi) {
    __nv_bfloat162 v = __floats2bfloat162_rn(lo, hi);
    return *(uint32_t*)&v;
}

// mma.sync m16n8k16 bf16 (A row-major, B col-major), fp32 accumulate.
DEVINL void mma_bf16(float* d, const uint32_t* a, const uint32_t* b) {
    asm volatile(
        "mma.sync.aligned.m16n8k16.row.col.f32.bf16.bf16.f32 "
        "{%0,%1,%2,%3}, {%4,%5,%6,%7}, {%8,%9}, {%0,%1,%2,%3};"
        : "+f"(d[0]), "+f"(d[1]), "+f"(d[2]), "+f"(d[3])
        : "r"(a[0]), "r"(a[1]), "r"(a[2]), "r"(a[3]), "r"(b[0]), "r"(b[1]));
}

// ---------------- register-resident 64-wide layer primitives ----------------
// Fragment convention (per warp, m-tile of 16 rows):
//   w[j][0] = rows lr,   cols j*8+2lc, j*8+2lc+1 (bf16x2); w[j][1] = rows lr+8.
// This layout is both the mma C-fragment (pair-packed) and the A-fragment
// (kword j*4+lc) of the next layer -> layers chain in registers.

DEVINL void init_bias(float acc[8][4], const float* __restrict__ bias, int lc) {
#pragma unroll
    for (int j = 0; j < 8; j++) {
        float b0 = bias[j * 8 + 2 * lc], b1 = bias[j * 8 + 2 * lc + 1];
        acc[j][0] = b0; acc[j][1] = b1; acc[j][2] = b0; acc[j][3] = b1;
    }
}
DEVINL void pack_words(const float acc[8][4], uint32_t w[8][2], bool relu) {
#pragma unroll
    for (int j = 0; j < 8; j++) {
        float a0 = acc[j][0], a1 = acc[j][1], a2 = acc[j][2], a3 = acc[j][3];
        if (relu) { a0 = fmaxf(a0, 0.f); a1 = fmaxf(a1, 0.f); a2 = fmaxf(a2, 0.f); a3 = fmaxf(a3, 0.f); }
        w[j][0] = pack_bf16x2(a0, a1);
        w[j][1] = pack_bf16x2(a2, a3);
    }
}
// one 64x64 layer on one m-tile
DEVINL void layer_mma(float acc[8][4], const uint32_t w[8][2],
                      const uint32_t* __restrict__ wT, int lr, int lc) {
#pragma unroll
    for (int kt = 0; kt < 4; kt++) {
        uint32_t a[4] = { w[2 * kt][0], w[2 * kt][1], w[2 * kt + 1][0], w[2 * kt + 1][1] };
#pragma unroll
        for (int j = 0; j < 8; j++) {
            uint32_t bb[2];
            bb[0] = wT[(j * 8 + lr) * 32 + kt * 8 + lc];
            bb[1] = wT[(j * 8 + lr) * 32 + kt * 8 + lc + 4];
            mma_bf16(acc[j], a, bb);
        }
    }
}
// one 64x64 layer on TWO m-tiles sharing each weight-fragment load
DEVINL void layer_mma2(float a0[8][4], float a1[8][4],
                       const uint32_t w0[8][2], const uint32_t w1[8][2],
                       const uint32_t* __restrict__ wT, int lr, int lc) {
#pragma unroll
    for (int kt = 0; kt < 4; kt++) {
        uint32_t x0[4] = { w0[2 * kt][0], w0[2 * kt][1], w0[2 * kt + 1][0], w0[2 * kt + 1][1] };
        uint32_t x1[4] = { w1[2 * kt][0], w1[2 * kt][1], w1[2 * kt + 1][0], w1[2 * kt + 1][1] };
#pragma unroll
        for (int j = 0; j < 8; j++) {
            uint32_t bb[2];
            bb[0] = wT[(j * 8 + lr) * 32 + kt * 8 + lc];
            bb[1] = wT[(j * 8 + lr) * 32 + kt * 8 + lc + 4];
            mma_bf16(a0[j], x0, bb);
            mma_bf16(a1[j], x1, bb);
        }
    }
}

// ============ kernel 0: convert all layer weights to bf16 W^T ============
__global__ void wprep_kernel(
    const float* __restrict__ preW, const float* __restrict__ postW,
    const float* __restrict__ mu2W, const float* __restrict__ q2W,
    const float* __restrict__ qregW)
{
    int tid = threadIdx.x;
    for (int idx = tid; idx < 6 * 2048; idx += 256) {
        int l = idx >> 11, r = idx & 2047, dout = r >> 5, kw = r & 31;
        const float* W;
        switch (l) {
            case 0: W = preW;         break;
            case 1: W = preW + 4096;  break;
            case 2: W = postW;        break;
            case 3: W = postW + 4096; break;
            case 4: W = mu2W;         break;
            default: W = q2W;         break;
        }
        d_wT[idx] = pack_bf16x2(W[(2 * kw) * 64 + dout], W[(2 * kw + 1) * 64 + dout]);
    }
    for (int idx = tid; idx < 1024; idx += 256) {
        int rh = idx >> 5, kw = idx & 31;
        d_wTq[idx] = pack_bf16x2(qregW[(64 + 2 * kw) * 32 + rh],
                                 qregW[(64 + 2 * kw + 1) * 32 + rh]);
    }
}

// ============ kernel 1: mu0 -> 2 pre layers -> transposed bf16 mu_preT ============
__global__ void __launch_bounds__(128) prep_kernel(
    const float* __restrict__ xv, const int* __restrict__ mask,
    const float* __restrict__ mu1, const float* __restrict__ preb)
{
    __shared__ uint32_t sS[64 * 36];    // [node][kword], stride 36 -> conflict-free writes
    int b  = blockIdx.x >> 6;
    int n0 = (blockIdx.x & 63) << 6;
    int tid = threadIdx.x, wid = tid >> 5, lane = tid & 31;
    int lr = lane >> 2, lc = lane & 3;
    int rl0 = wid * 16 + lr;
    int row0 = n0 + rl0;

    float xv0 = xv[b * N_ + row0],     xv8 = xv[b * N_ + row0 + 8];
    float mv0 = (float)mask[b * N_ + row0], mv8 = (float)mask[b * N_ + row0 + 8];

    uint32_t w[8][2];
#pragma unroll
    for (int j = 0; j < 8; j++) {
        int c0 = j * 8 + 2 * lc;
        float u0 = mu1[c0], u1 = mu1[c0 + 1];
        w[j][0] = pack_bf16x2(fmaxf(xv0 * u0, 0.f) * mv0, fmaxf(xv0 * u1, 0.f) * mv0);
        w[j][1] = pack_bf16x2(fmaxf(xv8 * u0, 0.f) * mv8, fmaxf(xv8 * u1, 0.f) * mv8);
    }
    float acc[8][4];
    init_bias(acc, preb, lc);       layer_mma(acc, w, d_wT,        lr, lc); pack_words(acc, w, true);
    init_bias(acc, preb + 64, lc);  layer_mma(acc, w, d_wT + 2048, lr, lc); pack_words(acc, w, true);

#pragma unroll
    for (int j = 0; j < 8; j++) {
        sS[rl0 * 36 + j * 4 + lc]       = w[j][0];
        sS[(rl0 + 8) * 36 + j * 4 + lc] = w[j][1];
    }
    __syncthreads();

    // transpose: word (dd, node-pair jp) = (bf16(node 2jp, dd), bf16(node 2jp+1, dd))
    int jp = tid & 31;
#pragma unroll
    for (int t = 0; t < 16; t++) {
        int dd = (tid >> 5) + t * 4;
        uint32_t w0 = sS[(2 * jp) * 36 + (dd >> 1)];
        uint32_t w1 = sS[(2 * jp + 1) * 36 + (dd >> 1)];
        uint32_t out = __byte_perm(w0, w1, (dd & 1) ? 0x7632 : 0x5410);
        d_mu_preT_bf16[(size_t)(b * 64 + dd) * (N_ / 2) + (n0 >> 1) + jp] = out;
    }
}

// ============ kernel 2: bf16 mma.sync GEMM: mu_pool = (adj @ mu_pre) * m ============
// 4-stage cp.async pipeline, CP_WAIT(2): prefetch issued 2 full iterations ahead.
constexpr int A_STRIDE = 36;
constexpr int B_WSTRIDE = 20;
constexpr int A_FLOATS = 128 * A_STRIDE;
constexpr int STAGE_WORDS = A_FLOATS + 64 * B_WSTRIDE;   // 5888
constexpr int GEMM_SMEM = 4 * STAGE_WORDS * 4;           // 94208 B -> 2 CTAs/SM

__global__ void __launch_bounds__(128, 2) gemm_kernel(
    const float* __restrict__ adj, const int* __restrict__ mask)
{
    extern __shared__ __align__(16) float smemf[];
    const uint32_t sm_base = smem_u32(smemf);
    int tid = threadIdx.x, wid = tid >> 5, lane = tid & 31;
    int b  = blockIdx.x >> 5;
    int m0 = (blockIdx.x & 31) << 7;
    const float* adjb = adj + (size_t)b * N_ * N_;
    const uint32_t* mub = d_mu_preT_bf16 + (size_t)b * 64 * (N_ / 2);

    auto load_stage = [&](int slot, int chunk) {
        uint32_t base = sm_base + (uint32_t)(slot * STAGE_WORDS) * 4u;
        int kb = chunk * 32;
#pragma unroll
        for (int t = 0; t < 8; t++) {
            int idx = tid + t * 128;
            int row = idx >> 3, seg = idx & 7;
            cp_async16(base + (uint32_t)(row * A_STRIDE * 4 + seg * 16),
                       adjb + (size_t)(m0 + row) * N_ + kb + seg * 4);
        }
        uint32_t bbase = base + A_FLOATS * 4u;
#pragma unroll
        for (int t = 0; t < 2; t++) {
            int idx = tid + t * 128;
            int row = idx >> 2, seg = idx & 3;
            cp_async16(bbase + (uint32_t)(row * B_WSTRIDE * 4 + seg * 16),
                       mub + (size_t)row * (N_ / 2) + kb / 2 + seg * 4);
        }
    };

    load_stage(0, 0); cp_commit();
    load_stage(1, 1); cp_commit();
    load_stage(2, 2); cp_commit();

    float acc[2][8][4];
#pragma unroll
    for (int mt = 0; mt < 2; mt++)
#pragma unroll
        for (int j = 0; j < 8; j++)
#pragma unroll
            for (int r = 0; r < 4; r++) acc[mt][j][r] = 0.0f;

    const int lr = lane >> 2, lc = lane & 3;
    const int wrow = wid * 32;

    for (int c = 0; c < 128; c++) {
        CP_WAIT(2);                  // chunk c resident; c+1,c+2 may be in flight
        __syncthreads();             // visibility + slot-reuse guard (slot (c-1)&3 now free)
        if (c + 3 < 128) load_stage((c + 3) & 3, c + 3);
        cp_commit();

        const float* sA = smemf + (c & 3) * STAGE_WORDS;
        const uint32_t* sB = (const uint32_t*)(sA + A_FLOATS);
#pragma unroll
        for (int kt = 0; kt < 2; kt++) {
            int k0 = kt * 16;
            uint32_t af[2][4], bf[8][2];
#pragma unroll
            for (int mt = 0; mt < 2; mt++) {
                int r = wrow + mt * 16 + lr;
                float2 p0 = *(const float2*)&sA[(r    ) * A_STRIDE + k0 + 2 * lc    ];
                float2 p1 = *(const float2*)&sA[(r + 8) * A_STRIDE + k0 + 2 * lc    ];
                float2 p2 = *(const float2*)&sA[(r    ) * A_STRIDE + k0 + 2 * lc + 8];
                float2 p3 = *(const float2*)&sA[(r + 8) * A_STRIDE + k0 + 2 * lc + 8];
                af[mt][0] = pack_bf16x2(p0.x, p0.y);
                af[mt][1] = pack_bf16x2(p1.x, p1.y);
                af[mt][2] = pack_bf16x2(p2.x, p2.y);
                af[mt][3] = pack_bf16x2(p3.x, p3.y);
            }
            int kw0 = kt * 8 + lc;
#pragma unroll
            for (int j = 0; j < 8; j++) {
                int n = j * 8 + lr;
                bf[j][0] = sB[n * B_WSTRIDE + kw0    ];
                bf[j][1] = sB[n * B_WSTRIDE + kw0 + 4];
            }
#pragma unroll
            for (int mt = 0; mt < 2; mt++)
#pragma unroll
                for (int j = 0; j < 8; j++)
                    mma_bf16(acc[mt][j], af[mt], bf[j]);
        }
    }

    // epilogue: mask, pack bf16, store kword layout [row][j*4+lc]
#pragma unroll
    for (int mt = 0; mt < 2; mt++) {
#pragma unroll
        for (int half = 0; half < 2; half++) {
            int row = m0 + wrow + mt * 16 + lr + half * 8;
            float mv = (float)mask[b * N_ + row];
            uint32_t* dst = d_mu_pool_b16 + (size_t)(b * N_ + row) * 32;
#pragma unroll
            for (int j = 0; j < 8; j++)
                dst[j * 4 + lc] = pack_bf16x2(acc[mt][j][half * 2] * mv,
                                              acc[mt][j][half * 2 + 1] * mv);
        }
    }
}

// ============ kernel 3: post layers, mu2, mu, pooled partials (2 m-tiles/warp) ============
__global__ void __launch_bounds__(128) post_kernel(
    const float* __restrict__ xv, const int* __restrict__ mask,
    const float* __restrict__ mu1,
    const float* __restrict__ postb, const float* __restrict__ mu2b)
{
    __shared__ float sP[4][64];
    int b  = blockIdx.x >> 5;
    int n0 = (blockIdx.x & 31) << 7;     // 128 nodes per block
    int tid = threadIdx.x, wid = tid >> 5, lane = tid & 31;
    int lr = lane >> 2, lc = lane & 3;
    int row0 = n0 + wid * 32 + lr;       // tile0: row0, row0+8
    int row1 = row0 + 16;                // tile1: row1, row1+8

    uint32_t w0[8][2], w1[8][2];
    {
        const uint32_t* s0 = d_mu_pool_b16 + (size_t)(b * N_ + row0) * 32;
        const uint32_t* s1 = d_mu_pool_b16 + (size_t)(b * N_ + row1) * 32;
#pragma unroll
        for (int j = 0; j < 8; j++) {
            w0[j][0] = s0[j * 4 + lc];  w0[j][1] = s0[8 * 32 + j * 4 + lc];
            w1[j][0] = s1[j * 4 + lc];  w1[j][1] = s1[8 * 32 + j * 4 + lc];
        }
    }
    float a0[8][4], a1[8][4];
    init_bias(a0, postb, lc);      init_bias(a1, postb, lc);
    layer_mma2(a0, a1, w0, w1, d_wT + 2 * 2048, lr, lc);
    pack_words(a0, w0, true);      pack_words(a1, w1, true);
    init_bias(a0, postb + 64, lc); init_bias(a1, postb + 64, lc);
    layer_mma2(a0, a1, w0, w1, d_wT + 3 * 2048, lr, lc);
    pack_words(a0, w0, true);      pack_words(a1, w1, true);
    init_bias(a0, mu2b, lc);       init_bias(a1, mu2b, lc);
    layer_mma2(a0, a1, w0, w1, d_wT + 4 * 2048, lr, lc);   // mu2, no relu

    float x0 = xv[b * N_ + row0],      x8  = xv[b * N_ + row0 + 8];
    float x16 = xv[b * N_ + row1],     x24 = xv[b * N_ + row1 + 8];
    float m0v = (float)mask[b * N_ + row0],  m8v  = (float)mask[b * N_ + row0 + 8];
    float m16v = (float)mask[b * N_ + row1], m24v = (float)mask[b * N_ + row1 + 8];
    uint32_t* d0 = d_mu_b16 + (size_t)(b * N_ + row0) * 32;
    uint32_t* d1 = d_mu_b16 + (size_t)(b * N_ + row1) * 32;

    float ps[8][2];
#pragma unroll
    for (int j = 0; j < 8; j++) {
        int c0 = j * 8 + 2 * lc;
        float u0 = mu1[c0], u1 = mu1[c0 + 1];
        float v00 = fmaxf(fmaxf(x0 * u0, 0.f) * m0v + a0[j][0] * m0v, 0.f);
        float v01 = fmaxf(fmaxf(x0 * u1, 0.f) * m0v + a0[j][1] * m0v, 0.f);
        float v80 = fmaxf(fmaxf(x8 * u0, 0.f) * m8v + a0[j][2] * m8v, 0.f);
        float v81 = fmaxf(fmaxf(x8 * u1, 0.f) * m8v + a0[j][3] * m8v, 0.f);
        float w00 = fmaxf(fmaxf(x16 * u0, 0.f) * m16v + a1[j][0] * m16v, 0.f);
        float w01 = fmaxf(fmaxf(x16 * u1, 0.f) * m16v + a1[j][1] * m16v, 0.f);
        float w80 = fmaxf(fmaxf(x24 * u0, 0.f) * m24v + a1[j][2] * m24v, 0.f);
        float w81 = fmaxf(fmaxf(x24 * u1, 0.f) * m24v + a1[j][3] * m24v, 0.f);
        d0[j * 4 + lc]          = pack_bf16x2(v00, v01);
        d0[8 * 32 + j * 4 + lc] = pack_bf16x2(v80, v81);
        d1[j * 4 + lc]          = pack_bf16x2(w00, w01);
        d1[8 * 32 + j * 4 + lc] = pack_bf16x2(w80, w81);
        ps[j][0] = x0 * v00 + x8 * v80 + x16 * w00 + x24 * w80;
        ps[j][1] = x0 * v01 + x8 * v81 + x16 * w01 + x24 * w81;
    }
#pragma unroll
    for (int j = 0; j < 8; j++) {
#pragma unroll
        for (int h = 0; h < 2; h++) {
            float t = ps[j][h];
            t += __shfl_xor_sync(0xffffffffu, t, 4);
            t += __shfl_xor_sync(0xffffffffu, t, 8);
            t += __shfl_xor_sync(0xffffffffu, t, 16);
            if (lr == 0) sP[wid][j * 8 + 2 * lc + h] = t;
        }
    }
    __syncthreads();
    if (tid < 64)
        d_partial[(b * 32 + (blockIdx.x & 31)) * 64 + tid] =
            sP[0][tid] + sP[1][tid] + sP[2][tid] + sP[3][tid];
}

// ============ kernel 4: q head, 2 m-tiles/warp (includes pooled->q1->c1 fold) ============
__global__ void __launch_bounds__(128) q_kernel(
    const int* __restrict__ mask,
    const float* __restrict__ q1W, const float* __restrict__ q1b,
    const float* __restrict__ qregW, const float* __restrict__ qregb,
    const float* __restrict__ q2b,
    const float* __restrict__ qW, const float* __restrict__ qb,
    float* __restrict__ out)
{
    __shared__ float pooled[64], q1s[64], c1s[32];
    int b  = blockIdx.x >> 5;
    int n0 = (blockIdx.x & 31) << 7;
    int tid = threadIdx.x, wid = tid >> 5, lane = tid & 31;
    int lr = lane >> 2, lc = lane & 3;

    if (tid < 64) {
        float s = 0.f;
#pragma unroll 8
        for (int t = 0; t < 32; t++) s += d_partial[(b * 32 + t) * 64 + tid];
        pooled[tid] = s;
    }
    __syncthreads();
    if (tid < 64) {
        float a = q1b[tid];
#pragma unroll 8
        for (int k = 0; k < 64; k++) a = fmaf(pooled[k], q1W[k * 64 + tid], a);
        q1s[tid] = a;
    }
    __syncthreads();
    if (tid < 32) {
        float c = qregb[tid];
#pragma unroll 8
        for (int k = 0; k < 64; k++) c = fmaf(q1s[k], qregW[k * 32 + tid], c);
        c1s[tid] = c;
    }
    __syncthreads();

    int row0 = n0 + wid * 32 + lr;
    int row1 = row0 + 16;
    uint32_t w0[8][2], w1[8][2];
    {
        const uint32_t* s0 = d_mu_b16 + (size_t)(b * N_ + row0) * 32;
        const uint32_t* s1 = d_mu_b16 + (size_t)(b * N_ + row1) * 32;
#pragma unroll
        for (int j = 0; j < 8; j++) {
            w0[j][0] = s0[j * 4 + lc];  w0[j][1] = s0[8 * 32 + j * 4 + lc];
            w1[j][0] = s1[j * 4 + lc];  w1[j][1] = s1[8 * 32 + j * 4 + lc];
        }
    }
    float a0[8][4], a1[8][4];
    init_bias(a0, q2b, lc); init_bias(a1, q2b, lc);
    layer_mma2(a0, a1, w0, w1, d_wT + 5 * 2048, lr, lc);    // q2 (no relu)
    pack_words(a0, w0, false); pack_words(a1, w1, false);

    // qreg mma: N=32, acc init = c1
    float qa0[4][4], qa1[4][4];
#pragma unroll
    for (int j = 0; j < 4; j++) {
        int c0 = j * 8 + 2 * lc;
        qa0[j][0] = qa0[j][2] = c1s[c0];
        qa0[j][1] = qa0[j][3] = c1s[c0 + 1];
        qa1[j][0] = qa1[j][2] = c1s[c0];
        qa1[j][1] = qa1[j][3] = c1s[c0 + 1];
    }
#pragma unroll
    for (int kt = 0; kt < 4; kt++) {
        uint32_t x0[4] = { w0[2 * kt][0], w0[2 * kt][1], w0[2 * kt + 1][0], w0[2 * kt + 1][1] };
        uint32_t x1[4] = { w1[2 * kt][0], w1[2 * kt][1], w1[2 * kt + 1][0], w1[2 * kt + 1][1] };
#pragma unroll
        for (int j = 0; j < 4; j++) {
            uint32_t bb[2];
            bb[0] = d_wTq[(j * 8 + lr) * 32 + kt * 8 + lc];
            bb[1] = d_wTq[(j * 8 + lr) * 32 + kt * 8 + lc + 4];
            mma_bf16(qa0[j], x0, bb);
            mma_bf16(qa1[j], x1, bb);
        }
    }
    // relu, multiply qW, row-sum over 32 cols, write 4 rows
    float s00 = 0.f, s08 = 0.f, s10 = 0.f, s18 = 0.f;
#pragma unroll
    for (int j = 0; j < 4; j++) {
        int c0 = j * 8 + 2 * lc;
        float wq0 = qW[c0], wq1 = qW[c0 + 1];
        s00 += fmaxf(qa0[j][0], 0.f) * wq0 + fmaxf(qa0[j][1], 0.f) * wq1;
        s08 += fmaxf(qa0[j][2], 0.f) * wq0 + fmaxf(qa0[j][3], 0.f) * wq1;
        s10 += fmaxf(qa1[j][0], 0.f) * wq0 + fmaxf(qa1[j][1], 0.f) * wq1;
        s18 += fmaxf(qa1[j][2], 0.f) * wq0 + fmaxf(qa1[j][3], 0.f) * wq1;
    }
#pragma unroll
    for (int d = 1; d <= 2; d <<= 1) {
        s00 += __shfl_xor_sync(0xffffffffu, s00, d);
        s08 += __shfl_xor_sync(0xffffffffu, s08, d);
        s10 += __shfl_xor_sync(0xffffffffu, s10, d);
        s18 += __shfl_xor_sync(0xffffffffu, s18, d);
    }
    if (lc == 0) {
        float q0 = s00 + qb[0], q8 = s08 + qb[0], q16 = s10 + qb[0], q24 = s18 + qb[0];
        if (mask[b * N_ + row0] == 0)      q0  = -99999.0f;
        if (mask[b * N_ + row0 + 8] == 0)  q8  = -99999.0f;
        if (mask[b * N_ + row1] == 0)      q16 = -99999.0f;
        if (mask[b * N_ + row1 + 8] == 0)  q24 = -99999.0f;
        out[b * N_ + row0]      = q0;
        out[b * N_ + row0 + 8]  = q8;
        out[b * N_ + row1]      = q16;
        out[b * N_ + row1 + 8]  = q24;
    }
}

// ================= launcher =================
extern "C" void kernel_launch(void* const* d_in, const int* in_sizes, int n_in,
                              void* d_out, int out_size) {
    const float* xv    = (const float*)d_in[0];
    const float* adj   = (const float*)d_in[2];   // edges_weight_adj (d_in[1] is the dead 'adj')
    const int*   mask  = (const int*)  d_in[3];
    const float* mu1   = (const float*)d_in[4];
    const float* mu2W  = (const float*)d_in[5];
    const float* mu2b  = (const float*)d_in[6];
    const float* preW  = (const float*)d_in[7];
    const float* preb  = (const float*)d_in[8];
    const float* postW = (const float*)d_in[9];
    const float* postb = (const float*)d_in[10];
    const float* q1W   = (const float*)d_in[11];
    const float* q1b   = (const float*)d_in[12];
    const float* q2W   = (const float*)d_in[13];
    const float* q2b   = (const float*)d_in[14];
    const float* qregW = (const float*)d_in[15];
    const float* qregb = (const float*)d_in[16];
    const float* qW    = (const float*)d_in[17];
    const float* qb    = (const float*)d_in[18];
    float* out = (float*)d_out;

    cudaFuncSetAttribute(gemm_kernel, cudaFuncAttributeMaxDynamicSharedMemorySize, GEMM_SMEM);

    wprep_kernel<<<1, 256>>>(preW, postW, mu2W, q2W, qregW);
    prep_kernel<<<512, 128>>>(xv, mask, mu1, preb);
    gemm_kernel<<<256, 128, GEMM_SMEM>>>(adj, mask);
    post_kernel<<<256, 128>>>(xv, mask, mu1, postb, mu2b);
    q_kernel<<<256, 128>>>(mask, q1W, q1b, qregW, qregb, q2b, qW, qb, out);
}

// round 10
// speedup vs baseline: 1.5353x; 1.0997x over previous
#include <cuda_runtime.h>
#include <cuda_bf16.h>
#include <cstdint>

#define DEVINL __device__ __forceinline__

constexpr int B_ = 8;
constexpr int N_ = 4096;

// ---------------- device scratch (no allocations allowed) ----------------
__device__ uint32_t d_Bfrag[(size_t)B_ * 131072];        // fragment-major mu_pre (GEMM B operand)
__device__ uint32_t d_mu_pool_b16[(size_t)B_ * N_ * 32]; // [B][N][32 kwords] bf16x2 dim-pairs
__device__ uint32_t d_mu_b16[(size_t)B_ * N_ * 32];      // final mu, bf16x2 dim-pairs
__device__ float    d_partial[B_ * 32 * 64];             // per-128-node-block pooled partials
__device__ uint32_t d_wT[6 * 2304];                      // 6 layers W^T bf16, padded stride 36
__device__ uint32_t d_wTq[1152];                         // qregW lower half W^T, stride 36

// ---------------- helpers ----------------
DEVINL uint32_t smem_u32(const void* p) {
    uint32_t a;
    asm("{ .reg .u64 t; cvta.to.shared.u64 t, %1; cvt.u32.u64 %0, t; }" : "=r"(a) : "l"(p));
    return a;
}
DEVINL void cp_async16(uint32_t dst, const void* src) {
    asm volatile("cp.async.cg.shared.global [%0], [%1], 16;\n" :: "r"(dst), "l"(src));
}
DEVINL void cp_commit() { asm volatile("cp.async.commit_group;\n" ::); }
#define CP_WAIT(n) asm volatile("cp.async.wait_group %0;\n" :: "n"(n))

DEVINL uint32_t pack_bf16x2(float lo, float hi) {
    __nv_bfloat162 v = __floats2bfloat162_rn(lo, hi);
    return *(uint32_t*)&v;
}

// mma.sync m16n8k16 bf16 (A row-major, B col-major), fp32 accumulate.
DEVINL void mma_bf16(float* d, const uint32_t* a, const uint32_t* b) {
    asm volatile(
        "mma.sync.aligned.m16n8k16.row.col.f32.bf16.bf16.f32 "
        "{%0,%1,%2,%3}, {%4,%5,%6,%7}, {%8,%9}, {%0,%1,%2,%3};"
        : "+f"(d[0]), "+f"(d[1]), "+f"(d[2]), "+f"(d[3])
        : "r"(a[0]), "r"(a[1]), "r"(a[2]), "r"(a[3]), "r"(b[0]), "r"(b[1]));
}

// ---------------- register-resident 64-wide layer primitives ----------------
// w[j][0] = rows lr, cols j*8+2lc..+1 (bf16x2); w[j][1] = rows lr+8.
// Weight tables (smem or global) use stride 36 words: (j*8+lr)*36 + kt*8+lc.

DEVINL void init_bias(float acc[8][4], const float* __restrict__ bias, int lc) {
#pragma unroll
    for (int j = 0; j < 8; j++) {
        float b0 = bias[j * 8 + 2 * lc], b1 = bias[j * 8 + 2 * lc + 1];
        acc[j][0] = b0; acc[j][1] = b1; acc[j][2] = b0; acc[j][3] = b1;
    }
}
DEVINL void pack_words(const float acc[8][4], uint32_t w[8][2], bool relu) {
#pragma unroll
    for (int j = 0; j < 8; j++) {
        float a0 = acc[j][0], a1 = acc[j][1], a2 = acc[j][2], a3 = acc[j][3];
        if (relu) { a0 = fmaxf(a0, 0.f); a1 = fmaxf(a1, 0.f); a2 = fmaxf(a2, 0.f); a3 = fmaxf(a3, 0.f); }
        w[j][0] = pack_bf16x2(a0, a1);
        w[j][1] = pack_bf16x2(a2, a3);
    }
}
DEVINL void layer_mma(float acc[8][4], const uint32_t w[8][2],
                      const uint32_t* __restrict__ wT, int lr, int lc) {
#pragma unroll
    for (int kt = 0; kt < 4; kt++) {
        uint32_t a[4] = { w[2 * kt][0], w[2 * kt][1], w[2 * kt + 1][0], w[2 * kt + 1][1] };
#pragma unroll
        for (int j = 0; j < 8; j++) {
            uint32_t bb[2];
            bb[0] = wT[(j * 8 + lr) * 36 + kt * 8 + lc];
            bb[1] = wT[(j * 8 + lr) * 36 + kt * 8 + lc + 4];
            mma_bf16(acc[j], a, bb);
        }
    }
}
DEVINL void layer_mma2(float a0[8][4], float a1[8][4],
                       const uint32_t w0[8][2], const uint32_t w1[8][2],
                       const uint32_t* __restrict__ wT, int lr, int lc) {
#pragma unroll
    for (int kt = 0; kt < 4; kt++) {
        uint32_t x0[4] = { w0[2 * kt][0], w0[2 * kt][1], w0[2 * kt + 1][0], w0[2 * kt + 1][1] };
        uint32_t x1[4] = { w1[2 * kt][0], w1[2 * kt][1], w1[2 * kt + 1][0], w1[2 * kt + 1][1] };
#pragma unroll
        for (int j = 0; j < 8; j++) {
            uint32_t bb[2];
            bb[0] = wT[(j * 8 + lr) * 36 + kt * 8 + lc];
            bb[1] = wT[(j * 8 + lr) * 36 + kt * 8 + lc + 4];
            mma_bf16(a0[j], x0, bb);
            mma_bf16(a1[j], x1, bb);
        }
    }
}

// ============ kernel 0: convert all layer weights to bf16 W^T (stride 36) ============
__global__ void wprep_kernel(
    const float* __restrict__ preW, const float* __restrict__ postW,
    const float* __restrict__ mu2W, const float* __restrict__ q2W,
    const float* __restrict__ qregW)
{
    int gid = blockIdx.x * 256 + threadIdx.x;
    int gstride = gridDim.x * 256;
    for (int idx = gid; idx < 6 * 2304; idx += gstride) {
        int l = idx / 2304, r = idx % 2304, dout = r / 36, col = r % 36;
        uint32_t v = 0;
        if (col < 32) {
            const float* W;
            switch (l) {
                case 0: W = preW;         break;
                case 1: W = preW + 4096;  break;
                case 2: W = postW;        break;
                case 3: W = postW + 4096; break;
                case 4: W = mu2W;         break;
                default: W = q2W;         break;
            }
            v = pack_bf16x2(W[(2 * col) * 64 + dout], W[(2 * col + 1) * 64 + dout]);
        }
        d_wT[idx] = v;
    }
    for (int idx = gid; idx < 1152; idx += gstride) {
        int rh = idx / 36, col = idx % 36;
        uint32_t v = 0;
        if (col < 32)
            v = pack_bf16x2(qregW[(64 + 2 * col) * 32 + rh],
                            qregW[(64 + 2 * col + 1) * 32 + rh]);
        d_wTq[idx] = v;
    }
}

// ============ kernel 1: mu0 -> 2 pre layers -> fragment-major d_Bfrag ============
__global__ void __launch_bounds__(128) prep_kernel(
    const float* __restrict__ xv, const int* __restrict__ mask,
    const float* __restrict__ mu1, const float* __restrict__ preb)
{
    __shared__ uint32_t sS[64 * 36];        // [node][kword] staging, stride 36
    __shared__ uint32_t sW[2 * 2304];       // layers 0,1 weights
    int b  = blockIdx.x >> 6;
    int n0 = (blockIdx.x & 63) << 6;
    int tid = threadIdx.x, wid = tid >> 5, lane = tid & 31;
    int lr = lane >> 2, lc = lane & 3;
    int rl0 = wid * 16 + lr;
    int row0 = n0 + rl0;

    for (int i = tid; i < 2 * 2304; i += 128) sW[i] = d_wT[i];

    float xv0 = xv[b * N_ + row0],     xv8 = xv[b * N_ + row0 + 8];
    float mv0 = (float)mask[b * N_ + row0], mv8 = (float)mask[b * N_ + row0 + 8];

    uint32_t w[8][2];
#pragma unroll
    for (int j = 0; j < 8; j++) {
        int c0 = j * 8 + 2 * lc;
        float u0 = mu1[c0], u1 = mu1[c0 + 1];
        w[j][0] = pack_bf16x2(fmaxf(xv0 * u0, 0.f) * mv0, fmaxf(xv0 * u1, 0.f) * mv0);
        w[j][1] = pack_bf16x2(fmaxf(xv8 * u0, 0.f) * mv8, fmaxf(xv8 * u1, 0.f) * mv8);
    }
    __syncthreads();
    float acc[8][4];
    init_bias(acc, preb, lc);       layer_mma(acc, w, sW,        lr, lc); pack_words(acc, w, true);
    init_bias(acc, preb + 64, lc);  layer_mma(acc, w, sW + 2304, lr, lc); pack_words(acc, w, true);

#pragma unroll
    for (int j = 0; j < 8; j++) {
        sS[rl0 * 36 + j * 4 + lc]       = w[j][0];
        sS[(rl0 + 8) * 36 + j * 4 + lc] = w[j][1];
    }
    __syncthreads();

    // scatter to fragment-major layout; warp handles j = 2*wid, 2*wid+1
    // lane -> (lrw = lane&7, lcw = lane>>3); slot = lcw*8 + lrw
    int lrw = lane & 7, lcw = lane >> 3;
    int c0 = n0 >> 5;                     // first chunk covered by this block
#pragma unroll
    for (int cl = 0; cl < 2; cl++)
#pragma unroll
        for (int kt = 0; kt < 2; kt++)
#pragma unroll
            for (int h = 0; h < 2; h++)
#pragma unroll
                for (int jj = 0; jj < 2; jj++) {
                    int j  = wid * 2 + jj;
                    int dd = j * 8 + lrw;
                    int jp = cl * 16 + kt * 8 + lcw + 4 * h;   // local node-pair
                    uint32_t w0 = sS[(2 * jp) * 36 + (dd >> 1)];
                    uint32_t w1 = sS[(2 * jp + 1) * 36 + (dd >> 1)];
                    uint32_t out = __byte_perm(w0, w1, (dd & 1) ? 0x7632 : 0x5410);
                    d_Bfrag[(size_t)b * 131072 + (size_t)(c0 + cl) * 1024 +
                            kt * 512 + h * 256 + j * 32 + lcw * 8 + lrw] = out;
                }
}

// ============ kernel 2: barrier-free warp-decoupled bf16 GEMM ============
// Each warp owns 32 M-rows: private 4-stage cp.async ring for A (stride 40,
// conflict-free LDS.64); B fragments via coalesced LDG from d_Bfrag (L1 reuse).
constexpr int A_STRIDE = 40;                      // words per row (160B)
constexpr int WSTAGE_WORDS = 32 * A_STRIDE;       // 1280 words = 5120B per warp-stage
constexpr int GEMM_SMEM = 4 * 4 * WSTAGE_WORDS * 4;  // 4 warps x 4 stages = 81920B

__global__ void __launch_bounds__(128, 2) gemm_kernel(
    const float* __restrict__ adj, const int* __restrict__ mask)
{
    extern __shared__ __align__(16) float smemf[];
    const uint32_t sm_base = smem_u32(smemf);
    int tid = threadIdx.x, wid = tid >> 5, lane = tid & 31;
    int b  = blockIdx.x >> 5;
    int m0 = (blockIdx.x & 31) << 7;
    const int wrow = wid * 32;
    const float* adjb = adj + (size_t)b * N_ * N_ + (size_t)(m0 + wrow) * N_;
    const uint32_t* bfb = d_Bfrag + (size_t)b * 131072;

    const uint32_t warpbase = sm_base + (uint32_t)(wid * 4 * WSTAGE_WORDS) * 4u;
    float* const warpf = smemf + wid * 4 * WSTAGE_WORDS;

    auto load_stage = [&](int slot, int chunk) {
        uint32_t base = warpbase + (uint32_t)(slot * WSTAGE_WORDS) * 4u;
        int kb = chunk * 32;
#pragma unroll
        for (int i = 0; i < 8; i++) {
            int idx = lane + i * 32;
            int row = idx >> 3, seg = idx & 7;
            cp_async16(base + (uint32_t)(row * A_STRIDE * 4 + seg * 16),
                       adjb + (size_t)row * N_ + kb + seg * 4);
        }
    };

    load_stage(0, 0); cp_commit();
    load_stage(1, 1); cp_commit();
    load_stage(2, 2); cp_commit();

    float acc[2][8][4];
#pragma unroll
    for (int mt = 0; mt < 2; mt++)
#pragma unroll
        for (int j = 0; j < 8; j++)
#pragma unroll
            for (int r = 0; r < 4; r++) acc[mt][j][r] = 0.0f;

    const int lr = lane >> 2, lc = lane & 3;
    const int bslot = lc * 8 + lr;        // word slot within a fragment line

    for (int c = 0; c < 128; c++) {
        CP_WAIT(2);                       // this thread's chunk-c group done
        __syncwarp();                     // cross-lane visibility within warp
        if (c + 3 < 128) load_stage((c + 3) & 3, c + 3);
        cp_commit();

        const float* sA = warpf + (c & 3) * WSTAGE_WORDS;
        const uint32_t* bc = bfb + (size_t)c * 1024;
#pragma unroll
        for (int kt = 0; kt < 2; kt++) {
            int k0 = kt * 16;
            uint32_t af[2][4], bf[8][2];
#pragma unroll
            for (int mt = 0; mt < 2; mt++) {
                int r = mt * 16 + lr;
                float2 p0 = *(const float2*)&sA[(r    ) * A_STRIDE + k0 + 2 * lc    ];
                float2 p1 = *(const float2*)&sA[(r + 8) * A_STRIDE + k0 + 2 * lc    ];
                float2 p2 = *(const float2*)&sA[(r    ) * A_STRIDE + k0 + 2 * lc + 8];
                float2 p3 = *(const float2*)&sA[(r + 8) * A_STRIDE + k0 + 2 * lc + 8];
                af[mt][0] = pack_bf16x2(p0.x, p0.y);
                af[mt][1] = pack_bf16x2(p1.x, p1.y);
                af[mt][2] = pack_bf16x2(p2.x, p2.y);
                af[mt][3] = pack_bf16x2(p3.x, p3.y);
            }
            const uint32_t* bk = bc + kt * 512;
#pragma unroll
            for (int j = 0; j < 8; j++) {
                bf[j][0] = bk[          j * 32 + bslot];
                bf[j][1] = bk[256 +     j * 32 + bslot];
            }
#pragma unroll
            for (int mt = 0; mt < 2; mt++)
#pragma unroll
                for (int j = 0; j < 8; j++)
                    mma_bf16(acc[mt][j], af[mt], bf[j]);
        }
    }

    // epilogue: mask, pack bf16, store kword layout [row][j*4+lc]
#pragma unroll
    for (int mt = 0; mt < 2; mt++) {
#pragma unroll
        for (int half = 0; half < 2; half++) {
            int row = m0 + wrow + mt * 16 + lr + half * 8;
            float mv = (float)mask[b * N_ + row];
            uint32_t* dst = d_mu_pool_b16 + (size_t)(b * N_ + row) * 32;
#pragma unroll
            for (int j = 0; j < 8; j++)
                dst[j * 4 + lc] = pack_bf16x2(acc[mt][j][half * 2] * mv,
                                              acc[mt][j][half * 2 + 1] * mv);
        }
    }
}

// ============ kernel 3: post layers, mu2, mu, pooled partials (2 m-tiles/warp) ============
__global__ void __launch_bounds__(128) post_kernel(
    const float* __restrict__ xv, const int* __restrict__ mask,
    const float* __restrict__ mu1,
    const float* __restrict__ postb, const float* __restrict__ mu2b)
{
    __shared__ uint32_t sW[3 * 2304];    // layers 2,3,4
    __shared__ float sP[4][64];
    int b  = blockIdx.x >> 5;
    int n0 = (blockIdx.x & 31) << 7;
    int tid = threadIdx.x, wid = tid >> 5, lane = tid & 31;
    int lr = lane >> 2, lc = lane & 3;
    int row0 = n0 + wid * 32 + lr;
    int row1 = row0 + 16;

    for (int i = tid; i < 3 * 2304; i += 128) sW[i] = d_wT[2 * 2304 + i];

    uint32_t w0[8][2], w1[8][2];
    {
        const uint32_t* s0 = d_mu_pool_b16 + (size_t)(b * N_ + row0) * 32;
        const uint32_t* s1 = d_mu_pool_b16 + (size_t)(b * N_ + row1) * 32;
#pragma unroll
        for (int j = 0; j < 8; j++) {
            w0[j][0] = s0[j * 4 + lc];  w0[j][1] = s0[8 * 32 + j * 4 + lc];
            w1[j][0] = s1[j * 4 + lc];  w1[j][1] = s1[8 * 32 + j * 4 + lc];
        }
    }
    __syncthreads();
    float a0[8][4], a1[8][4];
    init_bias(a0, postb, lc);      init_bias(a1, postb, lc);
    layer_mma2(a0, a1, w0, w1, sW, lr, lc);
    pack_words(a0, w0, true);      pack_words(a1, w1, true);
    init_bias(a0, postb + 64, lc); init_bias(a1, postb + 64, lc);
    layer_mma2(a0, a1, w0, w1, sW + 2304, lr, lc);
    pack_words(a0, w0, true);      pack_words(a1, w1, true);
    init_bias(a0, mu2b, lc);       init_bias(a1, mu2b, lc);
    layer_mma2(a0, a1, w0, w1, sW + 2 * 2304, lr, lc);   // mu2, no relu

    float x0 = xv[b * N_ + row0],      x8  = xv[b * N_ + row0 + 8];
    float x16 = xv[b * N_ + row1],     x24 = xv[b * N_ + row1 + 8];
    float m0v = (float)mask[b * N_ + row0],  m8v  = (float)mask[b * N_ + row0 + 8];
    float m16v = (float)mask[b * N_ + row1], m24v = (float)mask[b * N_ + row1 + 8];
    uint32_t* d0 = d_mu_b16 + (size_t)(b * N_ + row0) * 32;
    uint32_t* d1 = d_mu_b16 + (size_t)(b * N_ + row1) * 32;

    float ps[8][2];
#pragma unroll
    for (int j = 0; j < 8; j++) {
        int c0 = j * 8 + 2 * lc;
        float u0 = mu1[c0], u1 = mu1[c0 + 1];
        float v00 = fmaxf(fmaxf(x0 * u0, 0.f) * m0v + a0[j][0] * m0v, 0.f);
        float v01 = fmaxf(fmaxf(x0 * u1, 0.f) * m0v + a0[j][1] * m0v, 0.f);
        float v80 = fmaxf(fmaxf(x8 * u0, 0.f) * m8v + a0[j][2] * m8v, 0.f);
        float v81 = fmaxf(fmaxf(x8 * u1, 0.f) * m8v + a0[j][3] * m8v, 0.f);
        float q00 = fmaxf(fmaxf(x16 * u0, 0.f) * m16v + a1[j][0] * m16v, 0.f);
        float q01 = fmaxf(fmaxf(x16 * u1, 0.f) * m16v + a1[j][1] * m16v, 0.f);
        float q80 = fmaxf(fmaxf(x24 * u0, 0.f) * m24v + a1[j][2] * m24v, 0.f);
        float q81 = fmaxf(fmaxf(x24 * u1, 0.f) * m24v + a1[j][3] * m24v, 0.f);
        d0[j * 4 + lc]          = pack_bf16x2(v00, v01);
        d0[8 * 32 + j * 4 + lc] = pack_bf16x2(v80, v81);
        d1[j * 4 + lc]          = pack_bf16x2(q00, q01);
        d1[8 * 32 + j * 4 + lc] = pack_bf16x2(q80, q81);
        ps[j][0] = x0 * v00 + x8 * v80 + x16 * q00 + x24 * q80;
        ps[j][1] = x0 * v01 + x8 * v81 + x16 * q01 + x24 * q81;
    }
#pragma unroll
    for (int j = 0; j < 8; j++) {
#pragma unroll
        for (int h = 0; h < 2; h++) {
            float t = ps[j][h];
            t += __shfl_xor_sync(0xffffffffu, t, 4);
            t += __shfl_xor_sync(0xffffffffu, t, 8);
            t += __shfl_xor_sync(0xffffffffu, t, 16);
            if (lr == 0) sP[wid][j * 8 + 2 * lc + h] = t;
        }
    }
    __syncthreads();
    if (tid < 64)
        d_partial[(b * 32 + (blockIdx.x & 31)) * 64 + tid] =
            sP[0][tid] + sP[1][tid] + sP[2][tid] + sP[3][tid];
}

// ============ kernel 4: q head, 2 m-tiles/warp (includes pooled->q1->c1 fold) ============
__global__ void __launch_bounds__(128) q_kernel(
    const int* __restrict__ mask,
    const float* __restrict__ q1W, const float* __restrict__ q1b,
    const float* __restrict__ qregW, const float* __restrict__ qregb,
    const float* __restrict__ q2b,
    const float* __restrict__ qW, const float* __restrict__ qb,
    float* __restrict__ out)
{
    __shared__ uint32_t sW[2304 + 1152];   // q2 layer + qreg lower half
    __shared__ float pooled[64], q1s[64], c1s[32];
    __shared__ float red[2][64];
    int b  = blockIdx.x >> 5;
    int n0 = (blockIdx.x & 31) << 7;
    int tid = threadIdx.x, wid = tid >> 5, lane = tid & 31;
    int lr = lane >> 2, lc = lane & 3;

    for (int i = tid; i < 2304; i += 128) sW[i] = d_wT[5 * 2304 + i];
    for (int i = tid; i < 1152; i += 128) sW[2304 + i] = d_wTq[i];

    {   // pooled reduce: 2 groups over t, coalesced in d
        int d = tid & 63, g = tid >> 6;
        float s = 0.f;
#pragma unroll 4
        for (int t = g; t < 32; t += 2) s += d_partial[(b * 32 + t) * 64 + d];
        red[g][d] = s;
    }
    __syncthreads();
    if (tid < 64) pooled[tid] = red[0][tid] + red[1][tid];
    __syncthreads();
    if (tid < 64) {
        float a = q1b[tid];
#pragma unroll 8
        for (int k = 0; k < 64; k++) a = fmaf(pooled[k], q1W[k * 64 + tid], a);
        q1s[tid] = a;
    }
    __syncthreads();
    if (tid < 32) {
        float c = qregb[tid];
#pragma unroll 8
        for (int k = 0; k < 64; k++) c = fmaf(q1s[k], qregW[k * 32 + tid], c);
        c1s[tid] = c;
    }
    __syncthreads();

    int row0 = n0 + wid * 32 + lr;
    int row1 = row0 + 16;
    uint32_t w0[8][2], w1[8][2];
    {
        const uint32_t* s0 = d_mu_b16 + (size_t)(b * N_ + row0) * 32;
        const uint32_t* s1 = d_mu_b16 + (size_t)(b * N_ + row1) * 32;
#pragma unroll
        for (int j = 0; j < 8; j++) {
            w0[j][0] = s0[j * 4 + lc];  w0[j][1] = s0[8 * 32 + j * 4 + lc];
            w1[j][0] = s1[j * 4 + lc];  w1[j][1] = s1[8 * 32 + j * 4 + lc];
        }
    }
    float a0[8][4], a1[8][4];
    init_bias(a0, q2b, lc); init_bias(a1, q2b, lc);
    layer_mma2(a0, a1, w0, w1, sW, lr, lc);     // q2 (no relu)
    pack_words(a0, w0, false); pack_words(a1, w1, false);

    // qreg mma: N=32, acc init = c1
    float qa0[4][4], qa1[4][4];
#pragma unroll
    for (int j = 0; j < 4; j++) {
        int c0 = j * 8 + 2 * lc;
        qa0[j][0] = qa0[j][2] = c1s[c0];
        qa0[j][1] = qa0[j][3] = c1s[c0 + 1];
        qa1[j][0] = qa1[j][2] = c1s[c0];
        qa1[j][1] = qa1[j][3] = c1s[c0 + 1];
    }
    const uint32_t* sQ = sW + 2304;
#pragma unroll
    for (int kt = 0; kt < 4; kt++) {
        uint32_t x0[4] = { w0[2 * kt][0], w0[2 * kt][1], w0[2 * kt + 1][0], w0[2 * kt + 1][1] };
        uint32_t x1[4] = { w1[2 * kt][0], w1[2 * kt][1], w1[2 * kt + 1][0], w1[2 * kt + 1][1] };
#pragma unroll
        for (int j = 0; j < 4; j++) {
            uint32_t bb[2];
            bb[0] = sQ[(j * 8 + lr) * 36 + kt * 8 + lc];
            bb[1] = sQ[(j * 8 + lr) * 36 + kt * 8 + lc + 4];
            mma_bf16(qa0[j], x0, bb);
            mma_bf16(qa1[j], x1, bb);
        }
    }
    float s00 = 0.f, s08 = 0.f, s10 = 0.f, s18 = 0.f;
#pragma unroll
    for (int j = 0; j < 4; j++) {
        int c0 = j * 8 + 2 * lc;
        float wq0 = qW[c0], wq1 = qW[c0 + 1];
        s00 += fmaxf(qa0[j][0], 0.f) * wq0 + fmaxf(qa0[j][1], 0.f) * wq1;
        s08 += fmaxf(qa0[j][2], 0.f) * wq0 + fmaxf(qa0[j][3], 0.f) * wq1;
        s10 += fmaxf(qa1[j][0], 0.f) * wq0 + fmaxf(qa1[j][1], 0.f) * wq1;
        s18 += fmaxf(qa1[j][2], 0.f) * wq0 + fmaxf(qa1[j][3], 0.f) * wq1;
    }
#pragma unroll
    for (int d = 1; d <= 2; d <<= 1) {
        s00 += __shfl_xor_sync(0xffffffffu, s00, d);
        s08 += __shfl_xor_sync(0xffffffffu, s08, d);
        s10 += __shfl_xor_sync(0xffffffffu, s10, d);
        s18 += __shfl_xor_sync(0xffffffffu, s18, d);
    }
    if (lc == 0) {
        float q0 = s00 + qb[0], q8 = s08 + qb[0], q16 = s10 + qb[0], q24 = s18 + qb[0];
        if (mask[b * N_ + row0] == 0)      q0  = -99999.0f;
        if (mask[b * N_ + row0 + 8] == 0)  q8  = -99999.0f;
        if (mask[b * N_ + row1] == 0)      q16 = -99999.0f;
        if (mask[b * N_ + row1 + 8] == 0)  q24 = -99999.0f;
        out[b * N_ + row0]      = q0;
        out[b * N_ + row0 + 8]  = q8;
        out[b * N_ + row1]      = q16;
        out[b * N_ + row1 + 8]  = q24;
    }
}

// ================= launcher =================
extern "C" void kernel_launch(void* const* d_in, const int* in_sizes, int n_in,
                              void* d_out, int out_size) {
    const float* xv    = (const float*)d_in[0];
    const float* adj   = (const float*)d_in[2];   // edges_weight_adj (d_in[1] is the dead 'adj')
    const int*   mask  = (const int*)  d_in[3];
    const float* mu1   = (const float*)d_in[4];
    const float* mu2W  = (const float*)d_in[5];
    const float* mu2b  = (const float*)d_in[6];
    const float* preW  = (const float*)d_in[7];
    const float* preb  = (const float*)d_in[8];
    const float* postW = (const float*)d_in[9];
    const float* postb = (const float*)d_in[10];
    const float* q1W   = (const float*)d_in[11];
    const float* q1b   = (const float*)d_in[12];
    const float* q2W   = (const float*)d_in[13];
    const float* q2b   = (const float*)d_in[14];
    const float* qregW = (const float*)d_in[15];
    const float* qregb = (const float*)d_in[16];
    const float* qW    = (const float*)d_in[17];
    const float* qb    = (const float*)d_in[18];
    float* out = (float*)d_out;

    cudaFuncSetAttribute(gemm_kernel, cudaFuncAttributeMaxDynamicSharedMemorySize, GEMM_SMEM);

    wprep_kernel<<<64, 256>>>(preW, postW, mu2W, q2W, qregW);
    prep_kernel<<<512, 128>>>(xv, mask, mu1, preb);
    gemm_kernel<<<256, 128, GEMM_SMEM>>>(adj, mask);
    post_kernel<<<256, 128>>>(xv, mask, mu1, postb, mu2b);
    q_kernel<<<256, 128>>>(mask, q1W, q1b, qregW, qregb, q2b, qW, qb, out);
}

// round 11
// speedup vs baseline: 1.5395x; 1.0027x over previous
#include <cuda_runtime.h>
#include <cuda_bf16.h>
#include <cstdint>

#define DEVINL __device__ __forceinline__

constexpr int B_ = 8;
constexpr int N_ = 4096;

// ---------------- device scratch (no allocations allowed) ----------------
__device__ uint32_t d_Bfrag[(size_t)B_ * 131072];        // fragment-major mu_pre (GEMM B operand)
__device__ uint32_t d_mu_pool_b16[(size_t)B_ * N_ * 32]; // [B][N][32 kwords] bf16x2 dim-pairs
__device__ uint32_t d_mu_b16[(size_t)B_ * N_ * 32];      // final mu, bf16x2 dim-pairs
__device__ float    d_partial[B_ * 32 * 64];             // per-128-node-block pooled partials
__device__ uint32_t d_wT[6 * 2304];                      // 6 layers W^T bf16, padded stride 36
__device__ uint32_t d_wTq[1152];                         // qregW lower half W^T, stride 36

// ---------------- helpers ----------------
DEVINL uint32_t smem_u32(const void* p) {
    uint32_t a;
    asm("{ .reg .u64 t; cvta.to.shared.u64 t, %1; cvt.u32.u64 %0, t; }" : "=r"(a) : "l"(p));
    return a;
}
DEVINL void cp_async16(uint32_t dst, const void* src) {
    asm volatile("cp.async.cg.shared.global [%0], [%1], 16;\n" :: "r"(dst), "l"(src));
}
DEVINL void cp_commit() { asm volatile("cp.async.commit_group;\n" ::); }
#define CP_WAIT(n) asm volatile("cp.async.wait_group %0;\n" :: "n"(n))

DEVINL uint32_t pack_bf16x2(float lo, float hi) {
    __nv_bfloat162 v = __floats2bfloat162_rn(lo, hi);
    return *(uint32_t*)&v;
}

// mma.sync m16n8k16 bf16 (A row-major, B col-major), fp32 accumulate.
DEVINL void mma_bf16(float* d, const uint32_t* a, const uint32_t* b) {
    asm volatile(
        "mma.sync.aligned.m16n8k16.row.col.f32.bf16.bf16.f32 "
        "{%0,%1,%2,%3}, {%4,%5,%6,%7}, {%8,%9}, {%0,%1,%2,%3};"
        : "+f"(d[0]), "+f"(d[1]), "+f"(d[2]), "+f"(d[3])
        : "r"(a[0]), "r"(a[1]), "r"(a[2]), "r"(a[3]), "r"(b[0]), "r"(b[1]));
}

// ---------------- register-resident 64-wide layer primitives ----------------
// w[j][0] = rows lr, cols j*8+2lc..+1 (bf16x2); w[j][1] = rows lr+8.
// Weight tables (smem or global) use stride 36 words: (j*8+lr)*36 + kt*8+lc.

DEVINL void init_bias(float acc[8][4], const float* __restrict__ bias, int lc) {
#pragma unroll
    for (int j = 0; j < 8; j++) {
        float b0 = bias[j * 8 + 2 * lc], b1 = bias[j * 8 + 2 * lc + 1];
        acc[j][0] = b0; acc[j][1] = b1; acc[j][2] = b0; acc[j][3] = b1;
    }
}
DEVINL void pack_words(const float acc[8][4], uint32_t w[8][2], bool relu) {
#pragma unroll
    for (int j = 0; j < 8; j++) {
        float a0 = acc[j][0], a1 = acc[j][1], a2 = acc[j][2], a3 = acc[j][3];
        if (relu) { a0 = fmaxf(a0, 0.f); a1 = fmaxf(a1, 0.f); a2 = fmaxf(a2, 0.f); a3 = fmaxf(a3, 0.f); }
        w[j][0] = pack_bf16x2(a0, a1);
        w[j][1] = pack_bf16x2(a2, a3);
    }
}
DEVINL void layer_mma(float acc[8][4], const uint32_t w[8][2],
                      const uint32_t* __restrict__ wT, int lr, int lc) {
#pragma unroll
    for (int kt = 0; kt < 4; kt++) {
        uint32_t a[4] = { w[2 * kt][0], w[2 * kt][1], w[2 * kt + 1][0], w[2 * kt + 1][1] };
#pragma unroll
        for (int j = 0; j < 8; j++) {
            uint32_t bb[2];
            bb[0] = wT[(j * 8 + lr) * 36 + kt * 8 + lc];
            bb[1] = wT[(j * 8 + lr) * 36 + kt * 8 + lc + 4];
            mma_bf16(acc[j], a, bb);
        }
    }
}
DEVINL void layer_mma2(float a0[8][4], float a1[8][4],
                       const uint32_t w0[8][2], const uint32_t w1[8][2],
                       const uint32_t* __restrict__ wT, int lr, int lc) {
#pragma unroll
    for (int kt = 0; kt < 4; kt++) {
        uint32_t x0[4] = { w0[2 * kt][0], w0[2 * kt][1], w0[2 * kt + 1][0], w0[2 * kt + 1][1] };
        uint32_t x1[4] = { w1[2 * kt][0], w1[2 * kt][1], w1[2 * kt + 1][0], w1[2 * kt + 1][1] };
#pragma unroll
        for (int j = 0; j < 8; j++) {
            uint32_t bb[2];
            bb[0] = wT[(j * 8 + lr) * 36 + kt * 8 + lc];
            bb[1] = wT[(j * 8 + lr) * 36 + kt * 8 + lc + 4];
            mma_bf16(a0[j], x0, bb);
            mma_bf16(a1[j], x1, bb);
        }
    }
}

// ============ kernel 0: convert all layer weights to bf16 W^T (stride 36) ============
__global__ void wprep_kernel(
    const float* __restrict__ preW, const float* __restrict__ postW,
    const float* __restrict__ mu2W, const float* __restrict__ q2W,
    const float* __restrict__ qregW)
{
    int gid = blockIdx.x * 256 + threadIdx.x;
    int gstride = gridDim.x * 256;
    for (int idx = gid; idx < 6 * 2304; idx += gstride) {
        int l = idx / 2304, r = idx % 2304, dout = r / 36, col = r % 36;
        uint32_t v = 0;
        if (col < 32) {
            const float* W;
            switch (l) {
                case 0: W = preW;         break;
                case 1: W = preW + 4096;  break;
                case 2: W = postW;        break;
                case 3: W = postW + 4096; break;
                case 4: W = mu2W;         break;
                default: W = q2W;         break;
            }
            v = pack_bf16x2(W[(2 * col) * 64 + dout], W[(2 * col + 1) * 64 + dout]);
        }
        d_wT[idx] = v;
    }
    for (int idx = gid; idx < 1152; idx += gstride) {
        int rh = idx / 36, col = idx % 36;
        uint32_t v = 0;
        if (col < 32)
            v = pack_bf16x2(qregW[(64 + 2 * col) * 32 + rh],
                            qregW[(64 + 2 * col + 1) * 32 + rh]);
        d_wTq[idx] = v;
    }
}

// ============ kernel 1: mu0 -> 2 pre layers -> fragment-major d_Bfrag ============
__global__ void __launch_bounds__(128) prep_kernel(
    const float* __restrict__ xv, const int* __restrict__ mask,
    const float* __restrict__ mu1, const float* __restrict__ preb)
{
    __shared__ uint32_t sS[64 * 36];        // [node][kword] staging, stride 36
    __shared__ uint32_t sW[2 * 2304];       // layers 0,1 weights
    int b  = blockIdx.x >> 6;
    int n0 = (blockIdx.x & 63) << 6;
    int tid = threadIdx.x, wid = tid >> 5, lane = tid & 31;
    int lr = lane >> 2, lc = lane & 3;
    int rl0 = wid * 16 + lr;
    int row0 = n0 + rl0;

    for (int i = tid; i < 2 * 2304; i += 128) sW[i] = d_wT[i];

    float xv0 = xv[b * N_ + row0],     xv8 = xv[b * N_ + row0 + 8];
    float mv0 = (float)mask[b * N_ + row0], mv8 = (float)mask[b * N_ + row0 + 8];

    uint32_t w[8][2];
#pragma unroll
    for (int j = 0; j < 8; j++) {
        int c0 = j * 8 + 2 * lc;
        float u0 = mu1[c0], u1 = mu1[c0 + 1];
        w[j][0] = pack_bf16x2(fmaxf(xv0 * u0, 0.f) * mv0, fmaxf(xv0 * u1, 0.f) * mv0);
        w[j][1] = pack_bf16x2(fmaxf(xv8 * u0, 0.f) * mv8, fmaxf(xv8 * u1, 0.f) * mv8);
    }
    __syncthreads();
    float acc[8][4];
    init_bias(acc, preb, lc);       layer_mma(acc, w, sW,        lr, lc); pack_words(acc, w, true);
    init_bias(acc, preb + 64, lc);  layer_mma(acc, w, sW + 2304, lr, lc); pack_words(acc, w, true);

#pragma unroll
    for (int j = 0; j < 8; j++) {
        sS[rl0 * 36 + j * 4 + lc]       = w[j][0];
        sS[(rl0 + 8) * 36 + j * 4 + lc] = w[j][1];
    }
    __syncthreads();

    // scatter to fragment-major layout; warp handles j = 2*wid, 2*wid+1
    // lane -> (lrw = lane&7, lcw = lane>>3); slot = lcw*8 + lrw
    int lrw = lane & 7, lcw = lane >> 3;
    int c0 = n0 >> 5;                     // first chunk covered by this block
#pragma unroll
    for (int cl = 0; cl < 2; cl++)
#pragma unroll
        for (int kt = 0; kt < 2; kt++)
#pragma unroll
            for (int h = 0; h < 2; h++)
#pragma unroll
                for (int jj = 0; jj < 2; jj++) {
                    int j  = wid * 2 + jj;
                    int dd = j * 8 + lrw;
                    int jp = cl * 16 + kt * 8 + lcw + 4 * h;   // local node-pair
                    uint32_t w0 = sS[(2 * jp) * 36 + (dd >> 1)];
                    uint32_t w1 = sS[(2 * jp + 1) * 36 + (dd >> 1)];
                    uint32_t out = __byte_perm(w0, w1, (dd & 1) ? 0x7632 : 0x5410);
                    d_Bfrag[(size_t)b * 131072 + (size_t)(c0 + cl) * 1024 +
                            kt * 512 + h * 256 + j * 32 + lcw * 8 + lrw] = out;
                }
}

// ============ kernel 2: barrier-free warp-decoupled bf16 GEMM ============
// Each warp owns 32 M-rows: private 4-stage cp.async ring for A (stride 40,
// conflict-free LDS.64); B fragments via coalesced LDG from d_Bfrag (L1 reuse).
constexpr int A_STRIDE = 40;                      // words per row (160B)
constexpr int WSTAGE_WORDS = 32 * A_STRIDE;       // 1280 words = 5120B per warp-stage
constexpr int GEMM_SMEM = 4 * 4 * WSTAGE_WORDS * 4;  // 4 warps x 4 stages = 81920B

__global__ void __launch_bounds__(128, 2) gemm_kernel(
    const float* __restrict__ adj, const int* __restrict__ mask)
{
    extern __shared__ __align__(16) float smemf[];
    const uint32_t sm_base = smem_u32(smemf);
    int tid = threadIdx.x, wid = tid >> 5, lane = tid & 31;
    int b  = blockIdx.x >> 5;
    int m0 = (blockIdx.x & 31) << 7;
    const int wrow = wid * 32;
    const float* adjb = adj + (size_t)b * N_ * N_ + (size_t)(m0 + wrow) * N_;
    const uint32_t* bfb = d_Bfrag + (size_t)b * 131072;

    const uint32_t warpbase = sm_base + (uint32_t)(wid * 4 * WSTAGE_WORDS) * 4u;
    float* const warpf = smemf + wid * 4 * WSTAGE_WORDS;

    auto load_stage = [&](int slot, int chunk) {
        uint32_t base = warpbase + (uint32_t)(slot * WSTAGE_WORDS) * 4u;
        int kb = chunk * 32;
#pragma unroll
        for (int i = 0; i < 8; i++) {
            int idx = lane + i * 32;
            int row = idx >> 3, seg = idx & 7;
            cp_async16(base + (uint32_t)(row * A_STRIDE * 4 + seg * 16),
                       adjb + (size_t)row * N_ + kb + seg * 4);
        }
    };

    load_stage(0, 0); cp_commit();
    load_stage(1, 1); cp_commit();
    load_stage(2, 2); cp_commit();

    float acc[2][8][4];
#pragma unroll
    for (int mt = 0; mt < 2; mt++)
#pragma unroll
        for (int j = 0; j < 8; j++)
#pragma unroll
            for (int r = 0; r < 4; r++) acc[mt][j][r] = 0.0f;

    const int lr = lane >> 2, lc = lane & 3;
    const int bslot = lc * 8 + lr;        // word slot within a fragment line

    for (int c = 0; c < 128; c++) {
        CP_WAIT(2);                       // this thread's chunk-c group done
        __syncwarp();                     // cross-lane visibility within warp
        if (c + 3 < 128) load_stage((c + 3) & 3, c + 3);
        cp_commit();

        const float* sA = warpf + (c & 3) * WSTAGE_WORDS;
        const uint32_t* bc = bfb + (size_t)c * 1024;
#pragma unroll
        for (int kt = 0; kt < 2; kt++) {
            int k0 = kt * 16;
            uint32_t af[2][4], bf[8][2];
#pragma unroll
            for (int mt = 0; mt < 2; mt++) {
                int r = mt * 16 + lr;
                float2 p0 = *(const float2*)&sA[(r    ) * A_STRIDE + k0 + 2 * lc    ];
                float2 p1 = *(const float2*)&sA[(r + 8) * A_STRIDE + k0 + 2 * lc    ];
                float2 p2 = *(const float2*)&sA[(r    ) * A_STRIDE + k0 + 2 * lc + 8];
                float2 p3 = *(const float2*)&sA[(r + 8) * A_STRIDE + k0 + 2 * lc + 8];
                af[mt][0] = pack_bf16x2(p0.x, p0.y);
                af[mt][1] = pack_bf16x2(p1.x, p1.y);
                af[mt][2] = pack_bf16x2(p2.x, p2.y);
                af[mt][3] = pack_bf16x2(p3.x, p3.y);
            }
            const uint32_t* bk = bc + kt * 512;
#pragma unroll
            for (int j = 0; j < 8; j++) {
                bf[j][0] = bk[          j * 32 + bslot];
                bf[j][1] = bk[256 +     j * 32 + bslot];
            }
#pragma unroll
            for (int mt = 0; mt < 2; mt++)
#pragma unroll
                for (int j = 0; j < 8; j++)
                    mma_bf16(acc[mt][j], af[mt], bf[j]);
        }
    }

    // epilogue: mask, pack bf16, store kword layout [row][j*4+lc]
#pragma unroll
    for (int mt = 0; mt < 2; mt++) {
#pragma unroll
        for (int half = 0; half < 2; half++) {
            int row = m0 + wrow + mt * 16 + lr + half * 8;
            float mv = (float)mask[b * N_ + row];
            uint32_t* dst = d_mu_pool_b16 + (size_t)(b * N_ + row) * 32;
#pragma unroll
            for (int j = 0; j < 8; j++)
                dst[j * 4 + lc] = pack_bf16x2(acc[mt][j][half * 2] * mv,
                                              acc[mt][j][half * 2 + 1] * mv);
        }
    }
}

// ============ kernel 3: post layers, mu2, mu, pooled partials (2 m-tiles/warp) ============
__global__ void __launch_bounds__(128) post_kernel(
    const float* __restrict__ xv, const int* __restrict__ mask,
    const float* __restrict__ mu1,
    const float* __restrict__ postb, const float* __restrict__ mu2b)
{
    __shared__ uint32_t sW[3 * 2304];    // layers 2,3,4
    __shared__ float sP[4][64];
    int b  = blockIdx.x >> 5;
    int n0 = (blockIdx.x & 31) << 7;
    int tid = threadIdx.x, wid = tid >> 5, lane = tid & 31;
    int lr = lane >> 2, lc = lane & 3;
    int row0 = n0 + wid * 32 + lr;
    int row1 = row0 + 16;

    for (int i = tid; i < 3 * 2304; i += 128) sW[i] = d_wT[2 * 2304 + i];

    uint32_t w0[8][2], w1[8][2];
    {
        const uint32_t* s0 = d_mu_pool_b16 + (size_t)(b * N_ + row0) * 32;
        const uint32_t* s1 = d_mu_pool_b16 + (size_t)(b * N_ + row1) * 32;
#pragma unroll
        for (int j = 0; j < 8; j++) {
            w0[j][0] = s0[j * 4 + lc];  w0[j][1] = s0[8 * 32 + j * 4 + lc];
            w1[j][0] = s1[j * 4 + lc];  w1[j][1] = s1[8 * 32 + j * 4 + lc];
        }
    }
    __syncthreads();
    float a0[8][4], a1[8][4];
    init_bias(a0, postb, lc);      init_bias(a1, postb, lc);
    layer_mma2(a0, a1, w0, w1, sW, lr, lc);
    pack_words(a0, w0, true);      pack_words(a1, w1, true);
    init_bias(a0, postb + 64, lc); init_bias(a1, postb + 64, lc);
    layer_mma2(a0, a1, w0, w1, sW + 2304, lr, lc);
    pack_words(a0, w0, true);      pack_words(a1, w1, true);
    init_bias(a0, mu2b, lc);       init_bias(a1, mu2b, lc);
    layer_mma2(a0, a1, w0, w1, sW + 2 * 2304, lr, lc);   // mu2, no relu

    float x0 = xv[b * N_ + row0],      x8  = xv[b * N_ + row0 + 8];
    float x16 = xv[b * N_ + row1],     x24 = xv[b * N_ + row1 + 8];
    float m0v = (float)mask[b * N_ + row0],  m8v  = (float)mask[b * N_ + row0 + 8];
    float m16v = (float)mask[b * N_ + row1], m24v = (float)mask[b * N_ + row1 + 8];
    uint32_t* d0 = d_mu_b16 + (size_t)(b * N_ + row0) * 32;
    uint32_t* d1 = d_mu_b16 + (size_t)(b * N_ + row1) * 32;

    float ps[8][2];
#pragma unroll
    for (int j = 0; j < 8; j++) {
        int c0 = j * 8 + 2 * lc;
        float u0 = mu1[c0], u1 = mu1[c0 + 1];
        float v00 = fmaxf(fmaxf(x0 * u0, 0.f) * m0v + a0[j][0] * m0v, 0.f);
        float v01 = fmaxf(fmaxf(x0 * u1, 0.f) * m0v + a0[j][1] * m0v, 0.f);
        float v80 = fmaxf(fmaxf(x8 * u0, 0.f) * m8v + a0[j][2] * m8v, 0.f);
        float v81 = fmaxf(fmaxf(x8 * u1, 0.f) * m8v + a0[j][3] * m8v, 0.f);
        float q00 = fmaxf(fmaxf(x16 * u0, 0.f) * m16v + a1[j][0] * m16v, 0.f);
        float q01 = fmaxf(fmaxf(x16 * u1, 0.f) * m16v + a1[j][1] * m16v, 0.f);
        float q80 = fmaxf(fmaxf(x24 * u0, 0.f) * m24v + a1[j][2] * m24v, 0.f);
        float q81 = fmaxf(fmaxf(x24 * u1, 0.f) * m24v + a1[j][3] * m24v, 0.f);
        d0[j * 4 + lc]          = pack_bf16x2(v00, v01);
        d0[8 * 32 + j * 4 + lc] = pack_bf16x2(v80, v81);
        d1[j * 4 + lc]          = pack_bf16x2(q00, q01);
        d1[8 * 32 + j * 4 + lc] = pack_bf16x2(q80, q81);
        ps[j][0] = x0 * v00 + x8 * v80 + x16 * q00 + x24 * q80;
        ps[j][1] = x0 * v01 + x8 * v81 + x16 * q01 + x24 * q81;
    }
#pragma unroll
    for (int j = 0; j < 8; j++) {
#pragma unroll
        for (int h = 0; h < 2; h++) {
            float t = ps[j][h];
            t += __shfl_xor_sync(0xffffffffu, t, 4);
            t += __shfl_xor_sync(0xffffffffu, t, 8);
            t += __shfl_xor_sync(0xffffffffu, t, 16);
            if (lr == 0) sP[wid][j * 8 + 2 * lc + h] = t;
        }
    }
    __syncthreads();
    if (tid < 64)
        d_partial[(b * 32 + (blockIdx.x & 31)) * 64 + tid] =
            sP[0][tid] + sP[1][tid] + sP[2][tid] + sP[3][tid];
}

// ============ kernel 4: q head, 2 m-tiles/warp (includes pooled->q1->c1 fold) ============
__global__ void __launch_bounds__(128) q_kernel(
    const int* __restrict__ mask,
    const float* __restrict__ q1W, const float* __restrict__ q1b,
    const float* __restrict__ qregW, const float* __restrict__ qregb,
    const float* __restrict__ q2b,
    const float* __restrict__ qW, const float* __restrict__ qb,
    float* __restrict__ out)
{
    __shared__ uint32_t sW[2304 + 1152];   // q2 layer + qreg lower half
    __shared__ float pooled[64], q1s[64], c1s[32];
    __shared__ float red[2][64];
    int b  = blockIdx.x >> 5;
    int n0 = (blockIdx.x & 31) << 7;
    int tid = threadIdx.x, wid = tid >> 5, lane = tid & 31;
    int lr = lane >> 2, lc = lane & 3;

    for (int i = tid; i < 2304; i += 128) sW[i] = d_wT[5 * 2304 + i];
    for (int i = tid; i < 1152; i += 128) sW[2304 + i] = d_wTq[i];

    {   // pooled reduce: 2 groups over t, coalesced in d
        int d = tid & 63, g = tid >> 6;
        float s = 0.f;
#pragma unroll 4
        for (int t = g; t < 32; t += 2) s += d_partial[(b * 32 + t) * 64 + d];
        red[g][d] = s;
    }
    __syncthreads();
    if (tid < 64) pooled[tid] = red[0][tid] + red[1][tid];
    __syncthreads();
    if (tid < 64) {
        float a = q1b[tid];
#pragma unroll 8
        for (int k = 0; k < 64; k++) a = fmaf(pooled[k], q1W[k * 64 + tid], a);
        q1s[tid] = a;
    }
    __syncthreads();
    if (tid < 32) {
        float c = qregb[tid];
#pragma unroll 8
        for (int k = 0; k < 64; k++) c = fmaf(q1s[k], qregW[k * 32 + tid], c);
        c1s[tid] = c;
    }
    __syncthreads();

    int row0 = n0 + wid * 32 + lr;
    int row1 = row0 + 16;
    uint32_t w0[8][2], w1[8][2];
    {
        const uint32_t* s0 = d_mu_b16 + (size_t)(b * N_ + row0) * 32;
        const uint32_t* s1 = d_mu_b16 + (size_t)(b * N_ + row1) * 32;
#pragma unroll
        for (int j = 0; j < 8; j++) {
            w0[j][0] = s0[j * 4 + lc];  w0[j][1] = s0[8 * 32 + j * 4 + lc];
            w1[j][0] = s1[j * 4 + lc];  w1[j][1] = s1[8 * 32 + j * 4 + lc];
        }
    }
    float a0[8][4], a1[8][4];
    init_bias(a0, q2b, lc); init_bias(a1, q2b, lc);
    layer_mma2(a0, a1, w0, w1, sW, lr, lc);     // q2 (no relu)
    pack_words(a0, w0, false); pack_words(a1, w1, false);

    // qreg mma: N=32, acc init = c1
    float qa0[4][4], qa1[4][4];
#pragma unroll
    for (int j = 0; j < 4; j++) {
        int c0 = j * 8 + 2 * lc;
        qa0[j][0] = qa0[j][2] = c1s[c0];
        qa0[j][1] = qa0[j][3] = c1s[c0 + 1];
        qa1[j][0] = qa1[j][2] = c1s[c0];
        qa1[j][1] = qa1[j][3] = c1s[c0 + 1];
    }
    const uint32_t* sQ = sW + 2304;
#pragma unroll
    for (int kt = 0; kt < 4; kt++) {
        uint32_t x0[4] = { w0[2 * kt][0], w0[2 * kt][1], w0[2 * kt + 1][0], w0[2 * kt + 1][1] };
        uint32_t x1[4] = { w1[2 * kt][0], w1[2 * kt][1], w1[2 * kt + 1][0], w1[2 * kt + 1][1] };
#pragma unroll
        for (int j = 0; j < 4; j++) {
            uint32_t bb[2];
            bb[0] = sQ[(j * 8 + lr) * 36 + kt * 8 + lc];
            bb[1] = sQ[(j * 8 + lr) * 36 + kt * 8 + lc + 4];
            mma_bf16(qa0[j], x0, bb);
            mma_bf16(qa1[j], x1, bb);
        }
    }
    float s00 = 0.f, s08 = 0.f, s10 = 0.f, s18 = 0.f;
#pragma unroll
    for (int j = 0; j < 4; j++) {
        int c0 = j * 8 + 2 * lc;
        float wq0 = qW[c0], wq1 = qW[c0 + 1];
        s00 += fmaxf(qa0[j][0], 0.f) * wq0 + fmaxf(qa0[j][1], 0.f) * wq1;
        s08 += fmaxf(qa0[j][2], 0.f) * wq0 + fmaxf(qa0[j][3], 0.f) * wq1;
        s10 += fmaxf(qa1[j][0], 0.f) * wq0 + fmaxf(qa1[j][1], 0.f) * wq1;
        s18 += fmaxf(qa1[j][2], 0.f) * wq0 + fmaxf(qa1[j][3], 0.f) * wq1;
    }
#pragma unroll
    for (int d = 1; d <= 2; d <<= 1) {
        s00 += __shfl_xor_sync(0xffffffffu, s00, d);
        s08 += __shfl_xor_sync(0xffffffffu, s08, d);
        s10 += __shfl_xor_sync(0xffffffffu, s10, d);
        s18 += __shfl_xor_sync(0xffffffffu, s18, d);
    }
    if (lc == 0) {
        float q0 = s00 + qb[0], q8 = s08 + qb[0], q16 = s10 + qb[0], q24 = s18 + qb[0];
        if (mask[b * N_ + row0] == 0)      q0  = -99999.0f;
        if (mask[b * N_ + row0 + 8] == 0)  q8  = -99999.0f;
        if (mask[b * N_ + row1] == 0)      q16 = -99999.0f;
        if (mask[b * N_ + row1 + 8] == 0)  q24 = -99999.0f;
        out[b * N_ + row0]      = q0;
        out[b * N_ + row0 + 8]  = q8;
        out[b * N_ + row1]      = q16;
        out[b * N_ + row1 + 8]  = q24;
    }
}

// ================= launcher =================
extern "C" void kernel_launch(void* const* d_in, const int* in_sizes, int n_in,
                              void* d_out, int out_size) {
    const float* xv    = (const float*)d_in[0];
    const float* adj   = (const float*)d_in[2];   // edges_weight_adj (d_in[1] is the dead 'adj')
    const int*   mask  = (const int*)  d_in[3];
    const float* mu1   = (const float*)d_in[4];
    const float* mu2W  = (const float*)d_in[5];
    const float* mu2b  = (const float*)d_in[6];
    const float* preW  = (const float*)d_in[7];
    const float* preb  = (const float*)d_in[8];
    const float* postW = (const float*)d_in[9];
    const float* postb = (const float*)d_in[10];
    const float* q1W   = (const float*)d_in[11];
    const float* q1b   = (const float*)d_in[12];
    const float* q2W   = (const float*)d_in[13];
    const float* q2b   = (const float*)d_in[14];
    const float* qregW = (const float*)d_in[15];
    const float* qregb = (const float*)d_in[16];
    const float* qW    = (const float*)d_in[17];
    const float* qb    = (const float*)d_in[18];
    float* out = (float*)d_out;

    cudaFuncSetAttribute(gemm_kernel, cudaFuncAttributeMaxDynamicSharedMemorySize, GEMM_SMEM);

    wprep_kernel<<<64, 256>>>(preW, postW, mu2W, q2W, qregW);
    prep_kernel<<<512, 128>>>(xv, mask, mu1, preb);
    gemm_kernel<<<256, 128, GEMM_SMEM>>>(adj, mask);
    post_kernel<<<256, 128>>>(xv, mask, mu1, postb, mu2b);
    q_kernel<<<256, 128>>>(mask, q1W, q1b, qregW, qregb, q2b, qW, qb, out);
}

// round 12
// speedup vs baseline: 1.6019x; 1.0406x over previous
#include <cuda_runtime.h>
#include <cuda_bf16.h>
#include <cstdint>

#define DEVINL __device__ __forceinline__

constexpr int B_ = 8;
constexpr int N_ = 4096;

// ---------------- device scratch (no allocations allowed) ----------------
__device__ uint32_t d_Bfrag[(size_t)B_ * 131072];        // fragment-major mu_pre (GEMM B operand)
__device__ uint32_t d_mu_pool_b16[(size_t)B_ * N_ * 32]; // [B][N][32 kwords] bf16x2 dim-pairs
__device__ uint32_t d_mu_b16[(size_t)B_ * N_ * 32];      // final mu, bf16x2 dim-pairs
__device__ float    d_partial[B_ * 64 * 64];             // per-64-node-block pooled partials
__device__ uint32_t d_wT[6 * 2304];                      // 6 layers W^T bf16, padded stride 36
__device__ uint32_t d_wTq[1152];                         // qregW lower half W^T, stride 36

// ---------------- helpers ----------------
DEVINL uint32_t smem_u32(const void* p) {
    uint32_t a;
    asm("{ .reg .u64 t; cvta.to.shared.u64 t, %1; cvt.u32.u64 %0, t; }" : "=r"(a) : "l"(p));
    return a;
}
DEVINL void cp_async16(uint32_t dst, const void* src) {
    asm volatile("cp.async.cg.shared.global [%0], [%1], 16;\n" :: "r"(dst), "l"(src));
}
DEVINL void cp_commit() { asm volatile("cp.async.commit_group;\n" ::); }
#define CP_WAIT(n) asm volatile("cp.async.wait_group %0;\n" :: "n"(n))

DEVINL uint32_t pack_bf16x2(float lo, float hi) {
    __nv_bfloat162 v = __floats2bfloat162_rn(lo, hi);
    return *(uint32_t*)&v;
}

// mma.sync m16n8k16 bf16 (A row-major, B col-major), fp32 accumulate.
DEVINL void mma_bf16(float* d, const uint32_t* a, const uint32_t* b) {
    asm volatile(
        "mma.sync.aligned.m16n8k16.row.col.f32.bf16.bf16.f32 "
        "{%0,%1,%2,%3}, {%4,%5,%6,%7}, {%8,%9}, {%0,%1,%2,%3};"
        : "+f"(d[0]), "+f"(d[1]), "+f"(d[2]), "+f"(d[3])
        : "r"(a[0]), "r"(a[1]), "r"(a[2]), "r"(a[3]), "r"(b[0]), "r"(b[1]));
}

// ---------------- register-resident 64-wide layer primitives ----------------
// w[j][0] = rows lr, cols j*8+2lc..+1 (bf16x2); w[j][1] = rows lr+8.
// Weight tables use stride 36 words: (j*8+lr)*36 + kt*8+lc.

DEVINL void init_bias(float acc[8][4], const float* __restrict__ bias, int lc) {
#pragma unroll
    for (int j = 0; j < 8; j++) {
        float b0 = bias[j * 8 + 2 * lc], b1 = bias[j * 8 + 2 * lc + 1];
        acc[j][0] = b0; acc[j][1] = b1; acc[j][2] = b0; acc[j][3] = b1;
    }
}
DEVINL void pack_words(const float acc[8][4], uint32_t w[8][2], bool relu) {
#pragma unroll
    for (int j = 0; j < 8; j++) {
        float a0 = acc[j][0], a1 = acc[j][1], a2 = acc[j][2], a3 = acc[j][3];
        if (relu) { a0 = fmaxf(a0, 0.f); a1 = fmaxf(a1, 0.f); a2 = fmaxf(a2, 0.f); a3 = fmaxf(a3, 0.f); }
        w[j][0] = pack_bf16x2(a0, a1);
        w[j][1] = pack_bf16x2(a2, a3);
    }
}
DEVINL void layer_mma(float acc[8][4], const uint32_t w[8][2],
                      const uint32_t* __restrict__ wT, int lr, int lc) {
#pragma unroll
    for (int kt = 0; kt < 4; kt++) {
        uint32_t a[4] = { w[2 * kt][0], w[2 * kt][1], w[2 * kt + 1][0], w[2 * kt + 1][1] };
#pragma unroll
        for (int j = 0; j < 8; j++) {
            uint32_t bb[2];
            bb[0] = wT[(j * 8 + lr) * 36 + kt * 8 + lc];
            bb[1] = wT[(j * 8 + lr) * 36 + kt * 8 + lc + 4];
            mma_bf16(acc[j], a, bb);
        }
    }
}

// ============ kernel 0: convert all layer weights to bf16 W^T (stride 36) ============
__global__ void wprep_kernel(
    const float* __restrict__ preW, const float* __restrict__ postW,
    const float* __restrict__ mu2W, const float* __restrict__ q2W,
    const float* __restrict__ qregW)
{
    int gid = blockIdx.x * 256 + threadIdx.x;
    int gstride = gridDim.x * 256;
    for (int idx = gid; idx < 6 * 2304; idx += gstride) {
        int l = idx / 2304, r = idx % 2304, dout = r / 36, col = r % 36;
        uint32_t v = 0;
        if (col < 32) {
            const float* W;
            switch (l) {
                case 0: W = preW;         break;
                case 1: W = preW + 4096;  break;
                case 2: W = postW;        break;
                case 3: W = postW + 4096; break;
                case 4: W = mu2W;         break;
                default: W = q2W;         break;
            }
            v = pack_bf16x2(W[(2 * col) * 64 + dout], W[(2 * col + 1) * 64 + dout]);
        }
        d_wT[idx] = v;
    }
    for (int idx = gid; idx < 1152; idx += gstride) {
        int rh = idx / 36, col = idx % 36;
        uint32_t v = 0;
        if (col < 32)
            v = pack_bf16x2(qregW[(64 + 2 * col) * 32 + rh],
                            qregW[(64 + 2 * col + 1) * 32 + rh]);
        d_wTq[idx] = v;
    }
}

// ============ kernel 1: mu0 -> 2 pre layers -> fragment-major d_Bfrag ============
// d_Bfrag line layout (per chunk c): [kt][j][slot][h]  (h-pairs adjacent -> LDG.64 in gemm)
__global__ void __launch_bounds__(128) prep_kernel(
    const float* __restrict__ xv, const int* __restrict__ mask,
    const float* __restrict__ mu1, const float* __restrict__ preb)
{
    __shared__ uint32_t sS[64 * 36];        // [node][kword] staging, stride 36
    __shared__ uint32_t sW[2 * 2304];       // layers 0,1 weights
    int b  = blockIdx.x >> 6;
    int n0 = (blockIdx.x & 63) << 6;
    int tid = threadIdx.x, wid = tid >> 5, lane = tid & 31;
    int lr = lane >> 2, lc = lane & 3;
    int rl0 = wid * 16 + lr;
    int row0 = n0 + rl0;

    for (int i = tid; i < 2 * 2304 / 4; i += 128)
        ((uint4*)sW)[i] = ((const uint4*)d_wT)[i];

    float xv0 = xv[b * N_ + row0],     xv8 = xv[b * N_ + row0 + 8];
    float mv0 = (float)mask[b * N_ + row0], mv8 = (float)mask[b * N_ + row0 + 8];

    uint32_t w[8][2];
#pragma unroll
    for (int j = 0; j < 8; j++) {
        int c0 = j * 8 + 2 * lc;
        float u0 = mu1[c0], u1 = mu1[c0 + 1];
        w[j][0] = pack_bf16x2(fmaxf(xv0 * u0, 0.f) * mv0, fmaxf(xv0 * u1, 0.f) * mv0);
        w[j][1] = pack_bf16x2(fmaxf(xv8 * u0, 0.f) * mv8, fmaxf(xv8 * u1, 0.f) * mv8);
    }
    __syncthreads();
    float acc[8][4];
    init_bias(acc, preb, lc);       layer_mma(acc, w, sW,        lr, lc); pack_words(acc, w, true);
    init_bias(acc, preb + 64, lc);  layer_mma(acc, w, sW + 2304, lr, lc); pack_words(acc, w, true);

#pragma unroll
    for (int j = 0; j < 8; j++) {
        sS[rl0 * 36 + j * 4 + lc]       = w[j][0];
        sS[(rl0 + 8) * 36 + j * 4 + lc] = w[j][1];
    }
    __syncthreads();

    // scatter to fragment-major layout; warp handles j = 2*wid, 2*wid+1
    int lrw = lane & 7, lcw = lane >> 3;
    int slot = lcw * 8 + lrw;
    int c0 = n0 >> 5;                     // first chunk covered by this block
#pragma unroll
    for (int cl = 0; cl < 2; cl++)
#pragma unroll
        for (int kt = 0; kt < 2; kt++)
#pragma unroll
            for (int h = 0; h < 2; h++)
#pragma unroll
                for (int jj = 0; jj < 2; jj++) {
                    int j  = wid * 2 + jj;
                    int dd = j * 8 + lrw;
                    int jp = cl * 16 + kt * 8 + lcw + 4 * h;   // local node-pair
                    uint32_t w0 = sS[(2 * jp) * 36 + (dd >> 1)];
                    uint32_t w1 = sS[(2 * jp + 1) * 36 + (dd >> 1)];
                    uint32_t out = __byte_perm(w0, w1, (dd & 1) ? 0x7632 : 0x5410);
                    d_Bfrag[(size_t)b * 131072 + (size_t)(c0 + cl) * 1024 +
                            kt * 512 + j * 64 + slot * 2 + h] = out;
                }
}

// ============ kernel 2: warp-decoupled bf16 GEMM, 16 warps/SM ============
// Each warp owns 16 M-rows: private 4-stage cp.async ring for A (stride 40);
// B fragments via LDG.64 from interleaved d_Bfrag (L1 reuse across 16 warps).
constexpr int A_STRIDE = 40;                        // words per row (160B)
constexpr int WSTAGE_WORDS = 16 * A_STRIDE;         // 640 words = 2560B per warp-stage
constexpr int GEMM_SMEM = 8 * 4 * WSTAGE_WORDS * 4; // 8 warps x 4 stages = 81920B

__global__ void __launch_bounds__(256, 2) gemm_kernel(
    const float* __restrict__ adj, const int* __restrict__ mask)
{
    extern __shared__ __align__(16) float smemf[];
    const uint32_t sm_base = smem_u32(smemf);
    int tid = threadIdx.x, wid = tid >> 5, lane = tid & 31;
    int b  = blockIdx.x >> 5;
    int m0 = (blockIdx.x & 31) << 7;
    const int wrow = wid * 16;
    const float* adjb = adj + (size_t)b * N_ * N_ + (size_t)(m0 + wrow) * N_;
    const uint32_t* bfb = d_Bfrag + (size_t)b * 131072;

    const uint32_t warpbase = sm_base + (uint32_t)(wid * 4 * WSTAGE_WORDS) * 4u;
    float* const warpf = smemf + wid * 4 * WSTAGE_WORDS;

    auto load_stage = [&](int slot, int chunk) {
        uint32_t base = warpbase + (uint32_t)(slot * WSTAGE_WORDS) * 4u;
        int kb = chunk * 32;
#pragma unroll
        for (int i = 0; i < 4; i++) {
            int idx = lane + i * 32;
            int row = idx >> 3, seg = idx & 7;
            cp_async16(base + (uint32_t)(row * A_STRIDE * 4 + seg * 16),
                       adjb + (size_t)row * N_ + kb + seg * 4);
        }
    };

    load_stage(0, 0); cp_commit();
    load_stage(1, 1); cp_commit();
    load_stage(2, 2); cp_commit();

    float acc[8][4];
#pragma unroll
    for (int j = 0; j < 8; j++)
#pragma unroll
        for (int r = 0; r < 4; r++) acc[j][r] = 0.0f;

    const int lr = lane >> 2, lc = lane & 3;
    const int bslot = lc * 8 + lr;        // word-pair slot within a fragment line

    for (int c = 0; c < 128; c++) {
        CP_WAIT(2);                       // this warp's chunk-c group done
        __syncwarp();                     // cross-lane visibility within warp
        if (c + 3 < 128) load_stage((c + 3) & 3, c + 3);
        cp_commit();

        const float* sA = warpf + (c & 3) * WSTAGE_WORDS;
        const uint32_t* bc = bfb + (size_t)c * 1024;
#pragma unroll
        for (int kt = 0; kt < 2; kt++) {
            int k0 = kt * 16;
            uint32_t af[4];
            {
                float2 p0 = *(const float2*)&sA[(lr    ) * A_STRIDE + k0 + 2 * lc    ];
                float2 p1 = *(const float2*)&sA[(lr + 8) * A_STRIDE + k0 + 2 * lc    ];
                float2 p2 = *(const float2*)&sA[(lr    ) * A_STRIDE + k0 + 2 * lc + 8];
                float2 p3 = *(const float2*)&sA[(lr + 8) * A_STRIDE + k0 + 2 * lc + 8];
                af[0] = pack_bf16x2(p0.x, p0.y);
                af[1] = pack_bf16x2(p1.x, p1.y);
                af[2] = pack_bf16x2(p2.x, p2.y);
                af[3] = pack_bf16x2(p3.x, p3.y);
            }
            const uint32_t* bk = bc + kt * 512;
#pragma unroll
            for (int j = 0; j < 8; j++) {
                uint2 bv = *(const uint2*)&bk[j * 64 + bslot * 2];
                uint32_t bb[2] = { bv.x, bv.y };
                mma_bf16(acc[j], af, bb);
            }
        }
    }

    // epilogue: mask, pack bf16, store kword layout [row][j*4+lc]
#pragma unroll
    for (int half = 0; half < 2; half++) {
        int row = m0 + wrow + lr + half * 8;
        float mv = (float)mask[b * N_ + row];
        uint32_t* dst = d_mu_pool_b16 + (size_t)(b * N_ + row) * 32;
#pragma unroll
        for (int j = 0; j < 8; j++)
            dst[j * 4 + lc] = pack_bf16x2(acc[j][half * 2] * mv,
                                          acc[j][half * 2 + 1] * mv);
    }
}

// ============ kernel 3: post layers, mu2, mu, pooled partials (1 m-tile/warp) ============
__global__ void __launch_bounds__(128) post_kernel(
    const float* __restrict__ xv, const int* __restrict__ mask,
    const float* __restrict__ mu1,
    const float* __restrict__ postb, const float* __restrict__ mu2b)
{
    __shared__ uint32_t sW[3 * 2304];    // layers 2,3,4
    __shared__ float sP[4][64];
    int b  = blockIdx.x >> 6;
    int n0 = (blockIdx.x & 63) << 6;
    int tid = threadIdx.x, wid = tid >> 5, lane = tid & 31;
    int lr = lane >> 2, lc = lane & 3;
    int row0 = n0 + wid * 16 + lr;

    for (int i = tid; i < 3 * 2304 / 4; i += 128)
        ((uint4*)sW)[i] = ((const uint4*)(d_wT + 2 * 2304))[i];

    uint32_t w[8][2];
    {
        const uint32_t* s0 = d_mu_pool_b16 + (size_t)(b * N_ + row0) * 32;
#pragma unroll
        for (int j = 0; j < 8; j++) {
            w[j][0] = s0[j * 4 + lc];  w[j][1] = s0[8 * 32 + j * 4 + lc];
        }
    }
    __syncthreads();
    float acc[8][4];
    init_bias(acc, postb, lc);      layer_mma(acc, w, sW,            lr, lc); pack_words(acc, w, true);
    init_bias(acc, postb + 64, lc); layer_mma(acc, w, sW + 2304,     lr, lc); pack_words(acc, w, true);
    init_bias(acc, mu2b, lc);       layer_mma(acc, w, sW + 2 * 2304, lr, lc);   // mu2, no relu

    float x0 = xv[b * N_ + row0],      x8  = xv[b * N_ + row0 + 8];
    float m0v = (float)mask[b * N_ + row0],  m8v  = (float)mask[b * N_ + row0 + 8];
    uint32_t* d0 = d_mu_b16 + (size_t)(b * N_ + row0) * 32;

    float ps[8][2];
#pragma unroll
    for (int j = 0; j < 8; j++) {
        int c0 = j * 8 + 2 * lc;
        float u0 = mu1[c0], u1 = mu1[c0 + 1];
        float v00 = fmaxf(fmaxf(x0 * u0, 0.f) * m0v + acc[j][0] * m0v, 0.f);
        float v01 = fmaxf(fmaxf(x0 * u1, 0.f) * m0v + acc[j][1] * m0v, 0.f);
        float v80 = fmaxf(fmaxf(x8 * u0, 0.f) * m8v + acc[j][2] * m8v, 0.f);
        float v81 = fmaxf(fmaxf(x8 * u1, 0.f) * m8v + acc[j][3] * m8v, 0.f);
        d0[j * 4 + lc]          = pack_bf16x2(v00, v01);
        d0[8 * 32 + j * 4 + lc] = pack_bf16x2(v80, v81);
        ps[j][0] = x0 * v00 + x8 * v80;
        ps[j][1] = x0 * v01 + x8 * v81;
    }
#pragma unroll
    for (int j = 0; j < 8; j++) {
#pragma unroll
        for (int h = 0; h < 2; h++) {
            float t = ps[j][h];
            t += __shfl_xor_sync(0xffffffffu, t, 4);
            t += __shfl_xor_sync(0xffffffffu, t, 8);
            t += __shfl_xor_sync(0xffffffffu, t, 16);
            if (lr == 0) sP[wid][j * 8 + 2 * lc + h] = t;
        }
    }
    __syncthreads();
    if (tid < 64)
        d_partial[(b * 64 + (blockIdx.x & 63)) * 64 + tid] =
            sP[0][tid] + sP[1][tid] + sP[2][tid] + sP[3][tid];
}

// ============ kernel 4: q head, 1 m-tile/warp (includes pooled->q1->c1 fold) ============
__global__ void __launch_bounds__(128) q_kernel(
    const int* __restrict__ mask,
    const float* __restrict__ q1W, const float* __restrict__ q1b,
    const float* __restrict__ qregW, const float* __restrict__ qregb,
    const float* __restrict__ q2b,
    const float* __restrict__ qW, const float* __restrict__ qb,
    float* __restrict__ out)
{
    __shared__ uint32_t sW[2304 + 1152];   // q2 layer + qreg lower half
    __shared__ float pooled[64], q1s[64], c1s[32];
    __shared__ float red[2][64];
    int b  = blockIdx.x >> 6;
    int n0 = (blockIdx.x & 63) << 6;
    int tid = threadIdx.x, wid = tid >> 5, lane = tid & 31;
    int lr = lane >> 2, lc = lane & 3;

    for (int i = tid; i < (2304 + 1152) / 4; i += 128)
        ((uint4*)sW)[i] = (i < 2304 / 4) ? ((const uint4*)(d_wT + 5 * 2304))[i]
                                         : ((const uint4*)d_wTq)[i - 2304 / 4];

    {   // pooled reduce: 2 groups over t, coalesced in d
        int d = tid & 63, g = tid >> 6;
        float s = 0.f;
#pragma unroll 4
        for (int t = g; t < 64; t += 2) s += d_partial[(b * 64 + t) * 64 + d];
        red[g][d] = s;
    }
    __syncthreads();
    if (tid < 64) pooled[tid] = red[0][tid] + red[1][tid];
    __syncthreads();
    if (tid < 64) {
        float a = q1b[tid];
#pragma unroll 8
        for (int k = 0; k < 64; k++) a = fmaf(pooled[k], q1W[k * 64 + tid], a);
        q1s[tid] = a;
    }
    __syncthreads();
    if (tid < 32) {
        float c = qregb[tid];
#pragma unroll 8
        for (int k = 0; k < 64; k++) c = fmaf(q1s[k], qregW[k * 32 + tid], c);
        c1s[tid] = c;
    }
    __syncthreads();

    int row0 = n0 + wid * 16 + lr;
    uint32_t w[8][2];
    {
        const uint32_t* s0 = d_mu_b16 + (size_t)(b * N_ + row0) * 32;
#pragma unroll
        for (int j = 0; j < 8; j++) {
            w[j][0] = s0[j * 4 + lc];  w[j][1] = s0[8 * 32 + j * 4 + lc];
        }
    }
    float acc[8][4];
    init_bias(acc, q2b, lc);
    layer_mma(acc, w, sW, lr, lc);          // q2 (no relu)
    pack_words(acc, w, false);

    // qreg mma: N=32, acc init = c1
    float qa[4][4];
#pragma unroll
    for (int j = 0; j < 4; j++) {
        int c0 = j * 8 + 2 * lc;
        qa[j][0] = qa[j][2] = c1s[c0];
        qa[j][1] = qa[j][3] = c1s[c0 + 1];
    }
    const uint32_t* sQ = sW + 2304;
#pragma unroll
    for (int kt = 0; kt < 4; kt++) {
        uint32_t x0[4] = { w[2 * kt][0], w[2 * kt][1], w[2 * kt + 1][0], w[2 * kt + 1][1] };
#pragma unroll
        for (int j = 0; j < 4; j++) {
            uint32_t bb[2];
            bb[0] = sQ[(j * 8 + lr) * 36 + kt * 8 + lc];
            bb[1] = sQ[(j * 8 + lr) * 36 + kt * 8 + lc + 4];
            mma_bf16(qa[j], x0, bb);
        }
    }
    float s00 = 0.f, s08 = 0.f;
#pragma unroll
    for (int j = 0; j < 4; j++) {
        int c0 = j * 8 + 2 * lc;
        float wq0 = qW[c0], wq1 = qW[c0 + 1];
        s00 += fmaxf(qa[j][0], 0.f) * wq0 + fmaxf(qa[j][1], 0.f) * wq1;
        s08 += fmaxf(qa[j][2], 0.f) * wq0 + fmaxf(qa[j][3], 0.f) * wq1;
    }
#pragma unroll
    for (int d = 1; d <= 2; d <<= 1) {
        s00 += __shfl_xor_sync(0xffffffffu, s00, d);
        s08 += __shfl_xor_sync(0xffffffffu, s08, d);
    }
    if (lc == 0) {
        float q0 = s00 + qb[0], q8 = s08 + qb[0];
        if (mask[b * N_ + row0] == 0)      q0  = -99999.0f;
        if (mask[b * N_ + row0 + 8] == 0)  q8  = -99999.0f;
        out[b * N_ + row0]      = q0;
        out[b * N_ + row0 + 8]  = q8;
    }
}

// ================= launcher =================
extern "C" void kernel_launch(void* const* d_in, const int* in_sizes, int n_in,
                              void* d_out, int out_size) {
    const float* xv    = (const float*)d_in[0];
    const float* adj   = (const float*)d_in[2];   // edges_weight_adj (d_in[1] is the dead 'adj')
    const int*   mask  = (const int*)  d_in[3];
    const float* mu1   = (const float*)d_in[4];
    const float* mu2W  = (const float*)d_in[5];
    const float* mu2b  = (const float*)d_in[6];
    const float* preW  = (const float*)d_in[7];
    const float* preb  = (const float*)d_in[8];
    const float* postW = (const float*)d_in[9];
    const float* postb = (const float*)d_in[10];
    const float* q1W   = (const float*)d_in[11];
    const float* q1b   = (const float*)d_in[12];
    const float* q2W   = (const float*)d_in[13];
    const float* q2b   = (const float*)d_in[14];
    const float* qregW = (const float*)d_in[15];
    const float* qregb = (const float*)d_in[16];
    const float* qW    = (const float*)d_in[17];
    const float* qb    = (const float*)d_in[18];
    float* out = (float*)d_out;

    cudaFuncSetAttribute(gemm_kernel, cudaFuncAttributeMaxDynamicSharedMemorySize, GEMM_SMEM);

    wprep_kernel<<<64, 256>>>(preW, postW, mu2W, q2W, qregW);
    prep_kernel<<<512, 128>>>(xv, mask, mu1, preb);
    gemm_kernel<<<256, 256, GEMM_SMEM>>>(adj, mask);
    post_kernel<<<512, 128>>>(xv, mask, mu1, postb, mu2b);
    q_kernel<<<512, 128>>>(mask, q1W, q1b, qregW, qregb, q2b, qW, qb, out);
}